// round 1
// baseline (speedup 1.0000x reference)
#include <cuda_runtime.h>
#include <math.h>

#define BB 2
#define CC 128
#define HH 256      // 2*C
#define SS 4096     // 64*64 tokens
#define NH 4
#define DD 32       // head dim
#define TOK 16      // tokens per proj block
#define NTHR 256

#define QS 0.1767766952966369f   // 1/sqrt(32)

// ---------------- scratch (no allocation allowed) ----------------
__device__ float g_qp[BB*SS*CC];
__device__ float g_kp[BB*SS*CC];
__device__ float g_vp[BB*SS*CC];
__device__ float g_x [BB*SS*CC];
__device__ float g_r1[BB*SS*CC];

__device__ __forceinline__ const float* sel_in(int sel, const float* ext) {
    switch (sel) {
        case 0: return g_qp; case 1: return g_kp; case 2: return g_vp;
        case 3: return g_x;  case 4: return g_r1;
    }
    return ext;
}
__device__ __forceinline__ float* sel_out(int sel, float* ext) {
    switch (sel) {
        case 0: return g_qp; case 1: return g_kp; case 2: return g_vp;
        case 3: return g_x;  case 4: return g_r1;
    }
    return ext;
}

// ---------------- fused (LN) -> Linear(C,2C) -> LeakyReLU -> Linear(2C,C) (+res) ----------------
// One block = 16 tokens, 256 threads.
template<bool IN_CHW, bool HAS_LN, bool HAS_RES, bool OUT_CHW>
__global__ __launch_bounds__(NTHR)
void proj_kernel(const float* __restrict__ in_ext, int in_sel,
                 const float* __restrict__ gamma, const float* __restrict__ beta,
                 const float* __restrict__ w1, const float* __restrict__ b1,
                 const float* __restrict__ w2, const float* __restrict__ b2,
                 const float* __restrict__ res_ext, int res_sel,
                 float* __restrict__ out_ext, int out_sel)
{
    __shared__ __align__(16) float xln[CC*TOK];   // [c][t], t fastest (stride 16)
    __shared__ __align__(16) float hbuf[HH*20];   // [j][t], stride 20 (pad)
    __shared__ float mu_s[TOK], ri_s[TOK];

    const float* in  = sel_in(in_sel, in_ext);
    const float* res = HAS_RES ? sel_in(res_sel, res_ext) : nullptr;
    float*       out = sel_out(out_sel, out_ext);

    const int tid = threadIdx.x;
    const int bx  = blockIdx.x;
    const int b   = bx / (SS/TOK);
    const int s0  = (bx % (SS/TOK)) * TOK;

    // ---- load token tile into smem as xln[c][t] ----
    if (IN_CHW) {
        const float* base = in + (size_t)b*CC*SS + s0;
        for (int i = tid; i < CC*TOK; i += NTHR) {
            int c = i >> 4, t = i & 15;
            xln[i] = base[c*SS + t];
        }
    } else {
        const float* base = in + ((size_t)b*SS + s0)*CC;
        for (int i = tid; i < CC*TOK; i += NTHR) {
            int t = i >> 7, c = i & 127;
            xln[c*TOK + t] = base[t*CC + c];
        }
    }
    __syncthreads();

    // ---- layernorm over C per token ----
    if (HAS_LN) {
        if (tid < TOK) {
            float s = 0.f, s2 = 0.f;
            for (int c = 0; c < CC; c++) {
                float v = xln[c*TOK + tid];
                s += v; s2 += v*v;
            }
            float mu  = s * (1.0f/CC);
            float var = s2 * (1.0f/CC) - mu*mu;
            mu_s[tid] = mu;
            ri_s[tid] = rsqrtf(var + 1e-5f);
        }
        __syncthreads();
        for (int i = tid; i < CC*TOK; i += NTHR) {
            int c = i >> 4, t = i & 15;
            xln[i] = (xln[i] - mu_s[t]) * ri_s[t] * gamma[c] + beta[c];
        }
        __syncthreads();
    }

    // ---- stage 1: hidden column j = tid, all 16 tokens ----
    {
        const int j = tid;
        float acc[TOK];
        const float bj = b1[j];
        #pragma unroll
        for (int t = 0; t < TOK; t++) acc[t] = bj;
        const float* w1p = w1 + j;
        for (int c = 0; c < CC; c++) {
            const float w = w1p[c*HH];
            const float4* xr = reinterpret_cast<const float4*>(&xln[c*TOK]);
            #pragma unroll
            for (int g4 = 0; g4 < 4; g4++) {
                float4 a = xr[g4];
                acc[g4*4+0] = fmaf(a.x, w, acc[g4*4+0]);
                acc[g4*4+1] = fmaf(a.y, w, acc[g4*4+1]);
                acc[g4*4+2] = fmaf(a.z, w, acc[g4*4+2]);
                acc[g4*4+3] = fmaf(a.w, w, acc[g4*4+3]);
            }
        }
        #pragma unroll
        for (int t = 0; t < TOK; t++) {
            float v = acc[t];
            v = (v > 0.f) ? v : 0.01f * v;   // LeakyReLU(0.01)
            hbuf[j*20 + t] = v;
        }
    }
    __syncthreads();

    // ---- stage 2: out channel c, 8 tokens per thread ----
    {
        const int c  = tid & 127;
        const int t0 = (tid >> 7) * 8;
        float acc[8];
        const float bc = b2[c];
        #pragma unroll
        for (int t = 0; t < 8; t++) acc[t] = bc;
        const float* w2p = w2 + c;
        for (int j = 0; j < HH; j++) {
            const float w = w2p[j*CC];
            const float4* hr = reinterpret_cast<const float4*>(&hbuf[j*20 + t0]);
            float4 h0 = hr[0], h1 = hr[1];
            acc[0] = fmaf(h0.x, w, acc[0]);
            acc[1] = fmaf(h0.y, w, acc[1]);
            acc[2] = fmaf(h0.z, w, acc[2]);
            acc[3] = fmaf(h0.w, w, acc[3]);
            acc[4] = fmaf(h1.x, w, acc[4]);
            acc[5] = fmaf(h1.y, w, acc[5]);
            acc[6] = fmaf(h1.z, w, acc[6]);
            acc[7] = fmaf(h1.w, w, acc[7]);
        }
        if (HAS_RES) {
            const float* rb = res + ((size_t)b*SS + s0 + t0)*CC + c;
            #pragma unroll
            for (int t = 0; t < 8; t++) acc[t] += rb[t*CC];
        }
        if (OUT_CHW) {
            #pragma unroll
            for (int t = 0; t < 8; t++) xln[c*TOK + t0 + t] = acc[t];
        } else {
            float* ob = out + ((size_t)b*SS + s0 + t0)*CC + c;
            #pragma unroll
            for (int t = 0; t < 8; t++) ob[t*CC] = acc[t];
        }
    }
    if (OUT_CHW) {
        __syncthreads();
        float* base = out + (size_t)b*CC*SS + s0;
        for (int i = tid; i < CC*TOK; i += NTHR) {
            int c = i >> 4, t = i & 15;
            base[c*SS + t] = xln[i];
        }
    }
}

// ---------------- flash attention: 4 heads, d=32, S=4096 ----------------
// 1 query per thread, BM=256 queries/block, key tiles of 128 in smem,
// register score chunks of 8 (keeps unrolled body small vs I$).
#define BM 256
#define BN 128
#define CHK 8

__global__ __launch_bounds__(256)
void attn_kernel()
{
    __shared__ __align__(16) float Ks[BN*DD];
    __shared__ __align__(16) float Vs[BN*DD];

    const int tid = threadIdx.x;
    const int h   = blockIdx.y;
    const int b   = blockIdx.z;
    const int s   = blockIdx.x*BM + tid;

    // load q row, pre-scaled
    float q[DD];
    {
        const float* qb = g_qp + ((size_t)b*SS + s)*CC + h*DD;
        #pragma unroll
        for (int i4 = 0; i4 < 8; i4++) {
            float4 v = reinterpret_cast<const float4*>(qb)[i4];
            q[i4*4+0] = v.x*QS; q[i4*4+1] = v.y*QS;
            q[i4*4+2] = v.z*QS; q[i4*4+3] = v.w*QS;
        }
    }
    float o[DD];
    #pragma unroll
    for (int i = 0; i < DD; i++) o[i] = 0.f;
    float m = -1e30f, l = 0.f;

    const int row  = tid >> 1;       // 2 threads load each of 128 key rows
    const int half = (tid & 1) * 16;

    for (int kt = 0; kt < SS; kt += BN) {
        // load K/V tiles
        {
            const float* kb = g_kp + ((size_t)b*SS + kt + row)*CC + h*DD + half;
            const float* vb = g_vp + ((size_t)b*SS + kt + row)*CC + h*DD + half;
            float4* kd = reinterpret_cast<float4*>(&Ks[row*DD + half]);
            float4* vd = reinterpret_cast<float4*>(&Vs[row*DD + half]);
            #pragma unroll
            for (int i4 = 0; i4 < 4; i4++) {
                kd[i4] = reinterpret_cast<const float4*>(kb)[i4];
                vd[i4] = reinterpret_cast<const float4*>(vb)[i4];
            }
        }
        __syncthreads();

        for (int sub = 0; sub < BN; sub += CHK) {
            float sc[CHK];
            #pragma unroll
            for (int j = 0; j < CHK; j++) {
                const float4* kr = reinterpret_cast<const float4*>(&Ks[(sub+j)*DD]);
                float a = 0.f;
                #pragma unroll
                for (int i4 = 0; i4 < 8; i4++) {
                    float4 kv = kr[i4];
                    a = fmaf(q[i4*4+0], kv.x, a);
                    a = fmaf(q[i4*4+1], kv.y, a);
                    a = fmaf(q[i4*4+2], kv.z, a);
                    a = fmaf(q[i4*4+3], kv.w, a);
                }
                sc[j] = a;
            }
            float mc = sc[0];
            #pragma unroll
            for (int j = 1; j < CHK; j++) mc = fmaxf(mc, sc[j]);
            if (mc > m) {
                float corr = __expf(m - mc);
                l *= corr;
                #pragma unroll
                for (int i = 0; i < DD; i++) o[i] *= corr;
                m = mc;
            }
            #pragma unroll
            for (int j = 0; j < CHK; j++) {
                float p = __expf(sc[j] - m);
                l += p;
                const float4* vr = reinterpret_cast<const float4*>(&Vs[(sub+j)*DD]);
                #pragma unroll
                for (int i4 = 0; i4 < 8; i4++) {
                    float4 vv = vr[i4];
                    o[i4*4+0] = fmaf(p, vv.x, o[i4*4+0]);
                    o[i4*4+1] = fmaf(p, vv.y, o[i4*4+1]);
                    o[i4*4+2] = fmaf(p, vv.z, o[i4*4+2]);
                    o[i4*4+3] = fmaf(p, vv.w, o[i4*4+3]);
                }
            }
        }
        __syncthreads();
    }

    const float inv = 1.0f / l;
    float* ob = g_x + ((size_t)b*SS + s)*CC + h*DD;
    #pragma unroll
    for (int i4 = 0; i4 < 8; i4++) {
        float4 v;
        v.x = o[i4*4+0]*inv; v.y = o[i4*4+1]*inv;
        v.z = o[i4*4+2]*inv; v.w = o[i4*4+3]*inv;
        reinterpret_cast<float4*>(ob)[i4] = v;
    }
}

// ---------------- launcher ----------------
extern "C" void kernel_launch(void* const* d_in, const int* in_sizes, int n_in,
                              void* d_out, int out_size)
{
    (void)in_sizes; (void)n_in; (void)out_size;
    const float* q      = (const float*)d_in[0];
    const float* k      = (const float*)d_in[1];
    const float* v      = (const float*)d_in[2];
    const float* ln_q_g = (const float*)d_in[3];
    const float* ln_q_b = (const float*)d_in[4];
    const float* wq1    = (const float*)d_in[5];
    const float* bq1    = (const float*)d_in[6];
    const float* wq2    = (const float*)d_in[7];
    const float* bq2    = (const float*)d_in[8];
    const float* ln_k_g = (const float*)d_in[9];
    const float* ln_k_b = (const float*)d_in[10];
    const float* wk1    = (const float*)d_in[11];
    const float* bk1    = (const float*)d_in[12];
    const float* wk2    = (const float*)d_in[13];
    const float* bk2    = (const float*)d_in[14];
    const float* ln_v_g = (const float*)d_in[15];
    const float* ln_v_b = (const float*)d_in[16];
    const float* wv1    = (const float*)d_in[17];
    const float* bv1    = (const float*)d_in[18];
    const float* wv2    = (const float*)d_in[19];
    const float* bv2    = (const float*)d_in[20];
    const float* m1_w1  = (const float*)d_in[21];
    const float* m1_b1  = (const float*)d_in[22];
    const float* m1_w2  = (const float*)d_in[23];
    const float* m1_b2  = (const float*)d_in[24];
    const float* m2_w1  = (const float*)d_in[25];
    const float* m2_b1  = (const float*)d_in[26];
    const float* m2_w2  = (const float*)d_in[27];
    const float* m2_b2  = (const float*)d_in[28];
    float* out = (float*)d_out;

    const int nblk = BB * (SS/TOK);  // 512

    // q/k/v projections: CHW in, LN, BSC out to scratch 0/1/2
    proj_kernel<true,true,false,false><<<nblk, NTHR>>>(
        q, -1, ln_q_g, ln_q_b, wq1, bq1, wq2, bq2, nullptr, -1, nullptr, 0);
    proj_kernel<true,true,false,false><<<nblk, NTHR>>>(
        k, -1, ln_k_g, ln_k_b, wk1, bk1, wk2, bk2, nullptr, -1, nullptr, 1);
    proj_kernel<true,true,false,false><<<nblk, NTHR>>>(
        v, -1, ln_v_g, ln_v_b, wv1, bv1, wv2, bv2, nullptr, -1, nullptr, 2);

    // attention: g_qp/g_kp/g_vp -> g_x
    attn_kernel<<<dim3(SS/BM, NH, BB), 256>>>();

    // rs1 = vp + mlp1(x)   (in g_x, res g_vp, out g_r1)
    proj_kernel<false,false,true,false><<<nblk, NTHR>>>(
        nullptr, 3, nullptr, nullptr, m1_w1, m1_b1, m1_w2, m1_b2, nullptr, 2, nullptr, 4);

    // rs2 = rs1 + mlp2(rs1), write transposed CHW to d_out
    proj_kernel<false,false,true,true><<<nblk, NTHR>>>(
        nullptr, 4, nullptr, nullptr, m2_w1, m2_b1, m2_w2, m2_b2, nullptr, 4, out, -1);
}

// round 3
// speedup vs baseline: 2.2275x; 2.2275x over previous
#include <cuda_runtime.h>
#include <math.h>
#include <stdint.h>

#define BB 2
#define CC 128
#define HH 256      // 2*C
#define SS 4096     // 64*64 tokens
#define NH 4
#define DD 32       // head dim
#define TOK 16      // tokens per proj block
#define NTHR 256

#define QS 0.1767766952966369f   // 1/sqrt(32)

// ---------------- scratch (no allocation allowed) ----------------
__device__ float g_qp[BB*SS*CC];
__device__ float g_kp[BB*SS*CC];
__device__ float g_vp[BB*SS*CC];
__device__ float g_x [BB*SS*CC];
__device__ float g_r1[BB*SS*CC];

__device__ __forceinline__ const float* sel_in(int sel, const float* ext) {
    switch (sel) {
        case 0: return g_qp; case 1: return g_kp; case 2: return g_vp;
        case 3: return g_x;  case 4: return g_r1;
    }
    return ext;
}
__device__ __forceinline__ float* sel_out(int sel, float* ext) {
    switch (sel) {
        case 0: return g_qp; case 1: return g_kp; case 2: return g_vp;
        case 3: return g_x;  case 4: return g_r1;
    }
    return ext;
}

// tf32 mma m16n8k8 row.col: D += A*B  (A 16x8 row-major, B 8x8 col-major)
__device__ __forceinline__ void mma_tf32(float* c, const uint32_t* a, uint32_t b0, uint32_t b1) {
    asm volatile(
        "mma.sync.aligned.m16n8k8.row.col.f32.tf32.tf32.f32 "
        "{%0,%1,%2,%3}, {%4,%5,%6,%7}, {%8,%9}, {%0,%1,%2,%3};"
        : "+f"(c[0]), "+f"(c[1]), "+f"(c[2]), "+f"(c[3])
        : "r"(a[0]), "r"(a[1]), "r"(a[2]), "r"(a[3]), "r"(b0), "r"(b1));
}

// ================= mma.sync tf32 flash attention =================
// grid (64, 4, 2), 128 threads (4 warps). BM=64 (16 q-rows/warp), BN=64 keys/tile.
#define KVSTRIDE 36   // floats per smem row (conflict-free padding)

__global__ __launch_bounds__(128) void attn_mma_kernel()
{
    __shared__ __align__(16) float Ks[64*KVSTRIDE];
    __shared__ __align__(16) float Vs[64*KVSTRIDE];

    const int tid  = threadIdx.x;
    const int wid  = tid >> 5;
    const int lane = tid & 31;
    const int g    = lane >> 2;   // groupID (row within fragment)
    const int t    = lane & 3;    // threadID in group (col selector)
    const int h = blockIdx.y, b = blockIdx.z;
    const int q0 = blockIdx.x * 64;

    const float* qg = g_qp + ((size_t)b*SS)*CC + h*DD;
    const float* kg = g_kp + ((size_t)b*SS)*CC + h*DD;
    const float* vg = g_vp + ((size_t)b*SS)*CC + h*DD;

    // ---- load Q A-fragments (pre-scaled by QS), tf32 = truncated f32 bits ----
    uint32_t qa[4][4];
    {
        const int r0 = q0 + wid*16 + g;
        const float* qrow0 = qg + (size_t)r0*CC;
        const float* qrow1 = qrow0 + 8*CC;
        #pragma unroll
        for (int kt = 0; kt < 4; kt++) {
            qa[kt][0] = __float_as_uint(qrow0[kt*8 + t]     * QS);
            qa[kt][1] = __float_as_uint(qrow1[kt*8 + t]     * QS);
            qa[kt][2] = __float_as_uint(qrow0[kt*8 + t + 4] * QS);
            qa[kt][3] = __float_as_uint(qrow1[kt*8 + t + 4] * QS);
        }
    }

    float O[4][4];
    #pragma unroll
    for (int j = 0; j < 4; j++)
        #pragma unroll
        for (int i = 0; i < 4; i++) O[j][i] = 0.f;
    float m0 = -1e30f, m1 = -1e30f, l0 = 0.f, l1 = 0.f;

    const int srcA = (lane & ~3) | (t >> 1);
    const int srcB = srcA + 2;

    for (int tile = 0; tile < SS/64; tile++) {
        // ---- load K/V tile [64 x 32] into padded smem ----
        #pragma unroll
        for (int r = 0; r < 4; r++) {
            int idx = tid + r*128;            // 0..511
            int row = idx >> 3, c4 = idx & 7;
            size_t goff = (size_t)(tile*64 + row)*CC + c4*4;
            float4 kv = *reinterpret_cast<const float4*>(kg + goff);
            float4 vv = *reinterpret_cast<const float4*>(vg + goff);
            *reinterpret_cast<float4*>(&Ks[row*KVSTRIDE + c4*4]) = kv;
            *reinterpret_cast<float4*>(&Vs[row*KVSTRIDE + c4*4]) = vv;
        }
        __syncthreads();

        // ---- S = Q @ K^T : 8 n-tiles of 8 keys ----
        float s[8][4];
        #pragma unroll
        for (int jn = 0; jn < 8; jn++) {
            s[jn][0] = s[jn][1] = s[jn][2] = s[jn][3] = 0.f;
            const float* krow = &Ks[(jn*8 + g)*KVSTRIDE];
            #pragma unroll
            for (int kt = 0; kt < 4; kt++) {
                uint32_t b0 = __float_as_uint(krow[kt*8 + t]);
                uint32_t b1 = __float_as_uint(krow[kt*8 + t + 4]);
                mma_tf32(s[jn], qa[kt], b0, b1);
            }
        }

        // ---- online softmax ----
        float mt0 = s[0][0], mt1 = s[0][2];
        #pragma unroll
        for (int jn = 0; jn < 8; jn++) {
            mt0 = fmaxf(mt0, fmaxf(s[jn][0], s[jn][1]));
            mt1 = fmaxf(mt1, fmaxf(s[jn][2], s[jn][3]));
        }
        mt0 = fmaxf(mt0, __shfl_xor_sync(0xffffffffu, mt0, 1));
        mt0 = fmaxf(mt0, __shfl_xor_sync(0xffffffffu, mt0, 2));
        mt1 = fmaxf(mt1, __shfl_xor_sync(0xffffffffu, mt1, 1));
        mt1 = fmaxf(mt1, __shfl_xor_sync(0xffffffffu, mt1, 2));
        const float mn0 = fmaxf(m0, mt0), mn1 = fmaxf(m1, mt1);
        const float corr0 = __expf(m0 - mn0), corr1 = __expf(m1 - mn1);
        m0 = mn0; m1 = mn1;
        float ls0 = 0.f, ls1 = 0.f;
        #pragma unroll
        for (int jn = 0; jn < 8; jn++) {
            s[jn][0] = __expf(s[jn][0] - mn0); ls0 += s[jn][0];
            s[jn][1] = __expf(s[jn][1] - mn0); ls0 += s[jn][1];
            s[jn][2] = __expf(s[jn][2] - mn1); ls1 += s[jn][2];
            s[jn][3] = __expf(s[jn][3] - mn1); ls1 += s[jn][3];
        }
        l0 = l0*corr0 + ls0;
        l1 = l1*corr1 + ls1;
        #pragma unroll
        for (int j = 0; j < 4; j++) {
            O[j][0] *= corr0; O[j][1] *= corr0;
            O[j][2] *= corr1; O[j][3] *= corr1;
        }

        // ---- O += P @ V : convert P C-frag -> A-frag via shuffles ----
        #pragma unroll
        for (int kk = 0; kk < 8; kk++) {
            float v00 = __shfl_sync(0xffffffffu, s[kk][0], srcA);
            float v01 = __shfl_sync(0xffffffffu, s[kk][1], srcA);
            float v20 = __shfl_sync(0xffffffffu, s[kk][2], srcA);
            float v21 = __shfl_sync(0xffffffffu, s[kk][3], srcA);
            float w00 = __shfl_sync(0xffffffffu, s[kk][0], srcB);
            float w01 = __shfl_sync(0xffffffffu, s[kk][1], srcB);
            float w20 = __shfl_sync(0xffffffffu, s[kk][2], srcB);
            float w21 = __shfl_sync(0xffffffffu, s[kk][3], srcB);
            uint32_t pa[4];
            pa[0] = __float_as_uint((t & 1) ? v01 : v00);
            pa[1] = __float_as_uint((t & 1) ? v21 : v20);
            pa[2] = __float_as_uint((t & 1) ? w01 : w00);
            pa[3] = __float_as_uint((t & 1) ? w21 : w20);
            const float* vrow0 = &Vs[(kk*8 + t)*KVSTRIDE];
            const float* vrow1 = &Vs[(kk*8 + t + 4)*KVSTRIDE];
            #pragma unroll
            for (int jn = 0; jn < 4; jn++) {
                uint32_t b0 = __float_as_uint(vrow0[jn*8 + g]);
                uint32_t b1 = __float_as_uint(vrow1[jn*8 + g]);
                mma_tf32(O[jn], pa, b0, b1);
            }
        }
        __syncthreads();
    }

    // ---- epilogue: reduce l across quad, normalize, write ----
    l0 += __shfl_xor_sync(0xffffffffu, l0, 1);
    l0 += __shfl_xor_sync(0xffffffffu, l0, 2);
    l1 += __shfl_xor_sync(0xffffffffu, l1, 1);
    l1 += __shfl_xor_sync(0xffffffffu, l1, 2);
    const float inv0 = 1.0f / l0, inv1 = 1.0f / l1;
    const int r0 = q0 + wid*16 + g;
    float* o0 = g_x + ((size_t)b*SS + r0)*CC + h*DD;
    float* o1 = o0 + 8*CC;
    #pragma unroll
    for (int jn = 0; jn < 4; jn++) {
        float2 u0 = make_float2(O[jn][0]*inv0, O[jn][1]*inv0);
        float2 u1 = make_float2(O[jn][2]*inv1, O[jn][3]*inv1);
        *reinterpret_cast<float2*>(o0 + jn*8 + 2*t) = u0;
        *reinterpret_cast<float2*>(o1 + jn*8 + 2*t) = u1;
    }
}

// ---------------- fused (LN) -> Linear(C,2C) -> LeakyReLU -> Linear(2C,C) (+res) ----------------
template<bool IN_CHW, bool HAS_LN, bool HAS_RES, bool OUT_CHW>
__global__ __launch_bounds__(NTHR)
void proj_kernel(const float* __restrict__ in_ext, int in_sel,
                 const float* __restrict__ gamma, const float* __restrict__ beta,
                 const float* __restrict__ w1, const float* __restrict__ b1,
                 const float* __restrict__ w2, const float* __restrict__ b2,
                 const float* __restrict__ res_ext, int res_sel,
                 float* __restrict__ out_ext, int out_sel)
{
    __shared__ __align__(16) float xln[CC*TOK];   // [c][t]
    __shared__ __align__(16) float hbuf[HH*20];   // [j][t], stride 20
    __shared__ float mu_s[TOK], ri_s[TOK];

    const float* in  = sel_in(in_sel, in_ext);
    const float* res = HAS_RES ? sel_in(res_sel, res_ext) : nullptr;
    float*       out = sel_out(out_sel, out_ext);

    const int tid = threadIdx.x;
    const int bx  = blockIdx.x;
    const int b   = bx / (SS/TOK);
    const int s0  = (bx % (SS/TOK)) * TOK;

    if (IN_CHW) {
        const float* base = in + (size_t)b*CC*SS + s0;
        for (int i = tid; i < CC*TOK; i += NTHR) {
            int c = i >> 4, t = i & 15;
            xln[i] = base[c*SS + t];
        }
    } else {
        const float* base = in + ((size_t)b*SS + s0)*CC;
        for (int i = tid; i < CC*TOK; i += NTHR) {
            int t = i >> 7, c = i & 127;
            xln[c*TOK + t] = base[t*CC + c];
        }
    }
    __syncthreads();

    if (HAS_LN) {
        if (tid < TOK) {
            float s = 0.f, s2 = 0.f;
            for (int c = 0; c < CC; c++) {
                float v = xln[c*TOK + tid];
                s += v; s2 += v*v;
            }
            float mu  = s * (1.0f/CC);
            float var = s2 * (1.0f/CC) - mu*mu;
            mu_s[tid] = mu;
            ri_s[tid] = rsqrtf(var + 1e-5f);
        }
        __syncthreads();
        for (int i = tid; i < CC*TOK; i += NTHR) {
            int c = i >> 4, t = i & 15;
            xln[i] = (xln[i] - mu_s[t]) * ri_s[t] * gamma[c] + beta[c];
        }
        __syncthreads();
    }

    {
        const int j = tid;
        float acc[TOK];
        const float bj = b1[j];
        #pragma unroll
        for (int t = 0; t < TOK; t++) acc[t] = bj;
        const float* w1p = w1 + j;
        for (int c = 0; c < CC; c++) {
            const float w = w1p[c*HH];
            const float4* xr = reinterpret_cast<const float4*>(&xln[c*TOK]);
            #pragma unroll
            for (int g4 = 0; g4 < 4; g4++) {
                float4 a = xr[g4];
                acc[g4*4+0] = fmaf(a.x, w, acc[g4*4+0]);
                acc[g4*4+1] = fmaf(a.y, w, acc[g4*4+1]);
                acc[g4*4+2] = fmaf(a.z, w, acc[g4*4+2]);
                acc[g4*4+3] = fmaf(a.w, w, acc[g4*4+3]);
            }
        }
        #pragma unroll
        for (int t = 0; t < TOK; t++) {
            float v = acc[t];
            v = (v > 0.f) ? v : 0.01f * v;
            hbuf[j*20 + t] = v;
        }
    }
    __syncthreads();

    {
        const int c  = tid & 127;
        const int t0 = (tid >> 7) * 8;
        float acc[8];
        const float bc = b2[c];
        #pragma unroll
        for (int t = 0; t < 8; t++) acc[t] = bc;
        const float* w2p = w2 + c;
        for (int j = 0; j < HH; j++) {
            const float w = w2p[j*CC];
            const float4* hr = reinterpret_cast<const float4*>(&hbuf[j*20 + t0]);
            float4 h0 = hr[0], h1 = hr[1];
            acc[0] = fmaf(h0.x, w, acc[0]);
            acc[1] = fmaf(h0.y, w, acc[1]);
            acc[2] = fmaf(h0.z, w, acc[2]);
            acc[3] = fmaf(h0.w, w, acc[3]);
            acc[4] = fmaf(h1.x, w, acc[4]);
            acc[5] = fmaf(h1.y, w, acc[5]);
            acc[6] = fmaf(h1.z, w, acc[6]);
            acc[7] = fmaf(h1.w, w, acc[7]);
        }
        if (HAS_RES) {
            const float* rb = res + ((size_t)b*SS + s0 + t0)*CC + c;
            #pragma unroll
            for (int t = 0; t < 8; t++) acc[t] += rb[t*CC];
        }
        if (OUT_CHW) {
            #pragma unroll
            for (int t = 0; t < 8; t++) xln[c*TOK + t0 + t] = acc[t];
        } else {
            float* ob = out + ((size_t)b*SS + s0 + t0)*CC + c;
            #pragma unroll
            for (int t = 0; t < 8; t++) ob[t*CC] = acc[t];
        }
    }
    if (OUT_CHW) {
        __syncthreads();
        float* base = out + (size_t)b*CC*SS + s0;
        for (int i = tid; i < CC*TOK; i += NTHR) {
            int c = i >> 4, t = i & 15;
            base[c*SS + t] = xln[i];
        }
    }
}

// ---------------- launcher ----------------
extern "C" void kernel_launch(void* const* d_in, const int* in_sizes, int n_in,
                              void* d_out, int out_size)
{
    (void)in_sizes; (void)n_in; (void)out_size;
    const float* q      = (const float*)d_in[0];
    const float* k      = (const float*)d_in[1];
    const float* v      = (const float*)d_in[2];
    const float* ln_q_g = (const float*)d_in[3];
    const float* ln_q_b = (const float*)d_in[4];
    const float* wq1    = (const float*)d_in[5];
    const float* bq1    = (const float*)d_in[6];
    const float* wq2    = (const float*)d_in[7];
    const float* bq2    = (const float*)d_in[8];
    const float* ln_k_g = (const float*)d_in[9];
    const float* ln_k_b = (const float*)d_in[10];
    const float* wk1    = (const float*)d_in[11];
    const float* bk1    = (const float*)d_in[12];
    const float* wk2    = (const float*)d_in[13];
    const float* bk2    = (const float*)d_in[14];
    const float* ln_v_g = (const float*)d_in[15];
    const float* ln_v_b = (const float*)d_in[16];
    const float* wv1    = (const float*)d_in[17];
    const float* bv1    = (const float*)d_in[18];
    const float* wv2    = (const float*)d_in[19];
    const float* bv2    = (const float*)d_in[20];
    const float* m1_w1  = (const float*)d_in[21];
    const float* m1_b1  = (const float*)d_in[22];
    const float* m1_w2  = (const float*)d_in[23];
    const float* m1_b2  = (const float*)d_in[24];
    const float* m2_w1  = (const float*)d_in[25];
    const float* m2_b1  = (const float*)d_in[26];
    const float* m2_w2  = (const float*)d_in[27];
    const float* m2_b2  = (const float*)d_in[28];
    float* out = (float*)d_out;

    const int nblk = BB * (SS/TOK);  // 512

    proj_kernel<true,true,false,false><<<nblk, NTHR>>>(
        q, -1, ln_q_g, ln_q_b, wq1, bq1, wq2, bq2, nullptr, -1, nullptr, 0);
    proj_kernel<true,true,false,false><<<nblk, NTHR>>>(
        k, -1, ln_k_g, ln_k_b, wk1, bk1, wk2, bk2, nullptr, -1, nullptr, 1);
    proj_kernel<true,true,false,false><<<nblk, NTHR>>>(
        v, -1, ln_v_g, ln_v_b, wv1, bv1, wv2, bv2, nullptr, -1, nullptr, 2);

    // mma.sync tf32 flash attention: g_qp/g_kp/g_vp -> g_x
    attn_mma_kernel<<<dim3(SS/64, NH, BB), 128>>>();

    proj_kernel<false,false,true,false><<<nblk, NTHR>>>(
        nullptr, 3, nullptr, nullptr, m1_w1, m1_b1, m1_w2, m1_b2, nullptr, 2, nullptr, 4);

    proj_kernel<false,false,true,true><<<nblk, NTHR>>>(
        nullptr, 4, nullptr, nullptr, m2_w1, m2_b1, m2_w2, m2_b2, nullptr, 4, out, -1);
}

// round 4
// speedup vs baseline: 3.1607x; 1.4189x over previous
#include <cuda_runtime.h>
#include <math.h>
#include <stdint.h>

#define BB 2
#define CC 128
#define HH 256      // 2*C
#define SS 4096     // 64*64 tokens
#define NH 4
#define DD 32       // head dim

#define QS 0.1767766952966369f   // 1/sqrt(32)

// ---------------- scratch (no allocation allowed) ----------------
__device__ float g_qp[BB*SS*CC];
__device__ float g_kp[BB*SS*CC];
__device__ float g_vp[BB*SS*CC];
__device__ float g_x [BB*SS*CC];
__device__ float g_r1[BB*SS*CC];

__device__ __forceinline__ const float* sel_in(int sel, const float* ext) {
    switch (sel) {
        case 0: return g_qp; case 1: return g_kp; case 2: return g_vp;
        case 3: return g_x;  case 4: return g_r1;
    }
    return ext;
}
__device__ __forceinline__ float* sel_out(int sel, float* ext) {
    switch (sel) {
        case 0: return g_qp; case 1: return g_kp; case 2: return g_vp;
        case 3: return g_x;  case 4: return g_r1;
    }
    return ext;
}

// tf32 mma m16n8k8 row.col: D += A*B  (A 16x8 row-major, B 8x8 col-major)
__device__ __forceinline__ void mma_tf32(float* c, const uint32_t* a, uint32_t b0, uint32_t b1) {
    asm volatile(
        "mma.sync.aligned.m16n8k8.row.col.f32.tf32.tf32.f32 "
        "{%0,%1,%2,%3}, {%4,%5,%6,%7}, {%8,%9}, {%0,%1,%2,%3};"
        : "+f"(c[0]), "+f"(c[1]), "+f"(c[2]), "+f"(c[3])
        : "r"(a[0]), "r"(a[1]), "r"(a[2]), "r"(a[3]), "r"(b0), "r"(b1));
}
__device__ __forceinline__ float tf32rna(float x) {
    uint32_t r;
    asm("cvt.rna.tf32.f32 %0, %1;" : "=r"(r) : "f"(x));
    return __uint_as_float(r);
}
__device__ __forceinline__ uint32_t fbits(float x) { return __float_as_uint(x); }

// ================= tensor-core fused projection =================
// (LN) -> Linear(128,256) -> LeakyReLU(0.01) -> Linear(256,128) (+res)
// CTA: 64 tokens, 256 threads (8 warps: 4 m-groups x 2 n-groups). grid 128.
#define XSTR 132
#define HSTR 260
#define WSTR 72
// smem floats: X 64*132=8448, H 64*260=16640, W 128*72=9216, b1 256, b2 128,
// gamma 128, beta 128, mu 64, ri 64  -> 35072 floats = 140288 bytes
#define PROJ_SMEM_FLOATS (64*XSTR + 64*HSTR + 128*WSTR + 256 + 128 + 128 + 128 + 64 + 64)
#define PROJ_SMEM_BYTES (PROJ_SMEM_FLOATS*4)

template<int INMODE /*0=CHW+LN, 1=token-major*/, bool HAS_RES, bool OUT_CHW>
__global__ __launch_bounds__(256)
void proj_tc_kernel(const float* __restrict__ in_ext, int in_sel,
                    const float* __restrict__ gamma, const float* __restrict__ beta,
                    const float* __restrict__ w1, const float* __restrict__ b1,
                    const float* __restrict__ w2, const float* __restrict__ b2,
                    const float* __restrict__ res_ext, int res_sel,
                    float* __restrict__ out_ext, int out_sel)
{
    extern __shared__ float sm[];
    float* Xs  = sm;                    // [64][132]  (also Ys in epilogue)
    float* Hs  = Xs + 64*XSTR;          // [64][260]
    float* Ws  = Hs + 64*HSTR;          // [128][72]
    float* Bs1 = Ws + 128*WSTR;         // [256]
    float* Bs2 = Bs1 + 256;             // [128]
    float* Gs  = Bs2 + 128;             // [128]
    float* Bts = Gs + 128;              // [128]
    float* MUs = Bts + 128;             // [64]
    float* RIs = MUs + 64;              // [64]

    const float* in  = sel_in(in_sel, in_ext);
    const float* res = HAS_RES ? sel_in(res_sel, res_ext) : nullptr;
    float*       out = sel_out(out_sel, out_ext);

    const int tid  = threadIdx.x;
    const int wid  = tid >> 5;
    const int lane = tid & 31;
    const int g    = lane >> 2;
    const int t    = lane & 3;
    const int mrow  = (wid & 3) * 16;
    const int nhalf = (wid >> 2) * 32;

    const int gt0 = blockIdx.x * 64;     // global token base
    const int b   = gt0 >> 12;
    const int s0  = gt0 & (SS - 1);

    // ---- load biases (+ LN params) ----
    if (tid < 256) Bs1[tid] = b1[tid];
    if (tid < 128) Bs2[tid] = b2[tid];
    if (INMODE == 0 && tid < 128) { Gs[tid] = gamma[tid]; Bts[tid] = beta[tid]; }

    // ---- load X tile ----
    if (INMODE == 0) {
        const float* base = in + (size_t)b*CC*SS + s0;
        for (int i = tid; i < 64*CC; i += 256) {
            int c = i >> 6, tt = i & 63;
            Xs[tt*XSTR + c] = base[c*SS + tt];
        }
    } else {
        const float* base = in + (size_t)gt0*CC;
        for (int i = tid; i < 64*CC; i += 256) {
            int tt = i >> 7, c = i & 127;
            Xs[tt*XSTR + c] = tf32rna(base[i]);
        }
    }
    __syncthreads();

    if (INMODE == 0) {
        if (tid < 64) {
            float s = 0.f, s2 = 0.f;
            const float* xr = &Xs[tid*XSTR];
            for (int c = 0; c < CC; c++) { float v = xr[c]; s += v; s2 += v*v; }
            float mu = s * (1.0f/CC);
            float var = s2 * (1.0f/CC) - mu*mu;
            MUs[tid] = mu;
            RIs[tid] = rsqrtf(var + 1e-5f);
        }
        __syncthreads();
        for (int i = tid; i < 64*CC; i += 256) {
            int tt = i >> 7, c = i & 127;
            float v = Xs[tt*XSTR + c];
            v = (v - MUs[tt]) * RIs[tt] * Gs[c] + Bts[c];
            Xs[tt*XSTR + c] = tf32rna(v);
        }
        __syncthreads();
    }

    // ---- stage 1: H = leaky(X @ W1 + b1), N=256 in 4 chunks of 64 ----
    for (int nc = 0; nc < 4; nc++) {
        // load W1 chunk: rows k=0..127, cols nc*64..+64
        for (int i = tid; i < 128*16; i += 256) {
            int kk = i >> 4, j4 = i & 15;
            float4 wv = *reinterpret_cast<const float4*>(w1 + kk*HH + nc*64 + j4*4);
            float* d = &Ws[kk*WSTR + j4*4];
            d[0] = tf32rna(wv.x); d[1] = tf32rna(wv.y);
            d[2] = tf32rna(wv.z); d[3] = tf32rna(wv.w);
        }
        __syncthreads();

        float acc[4][4];
        #pragma unroll
        for (int jn = 0; jn < 4; jn++)
            acc[jn][0] = acc[jn][1] = acc[jn][2] = acc[jn][3] = 0.f;

        #pragma unroll
        for (int ks = 0; ks < 16; ks++) {
            uint32_t a[4];
            const float* x0 = &Xs[(mrow+g)*XSTR + ks*8];
            const float* x1 = x0 + 8*XSTR;
            a[0] = fbits(x0[t]); a[1] = fbits(x1[t]);
            a[2] = fbits(x0[t+4]); a[3] = fbits(x1[t+4]);
            #pragma unroll
            for (int jn = 0; jn < 4; jn++) {
                const float* wr = &Ws[(ks*8+t)*WSTR + nhalf + jn*8 + g];
                mma_tf32(acc[jn], a, fbits(wr[0]), fbits(wr[4*WSTR]));
            }
        }
        // bias + leaky + store H (tf32-converted)
        #pragma unroll
        for (int jn = 0; jn < 4; jn++) {
            int col = nc*64 + nhalf + jn*8 + 2*t;
            float c0 = acc[jn][0] + Bs1[col];
            float c1 = acc[jn][1] + Bs1[col+1];
            float c2 = acc[jn][2] + Bs1[col];
            float c3 = acc[jn][3] + Bs1[col+1];
            c0 = (c0 > 0.f) ? c0 : 0.01f*c0;
            c1 = (c1 > 0.f) ? c1 : 0.01f*c1;
            c2 = (c2 > 0.f) ? c2 : 0.01f*c2;
            c3 = (c3 > 0.f) ? c3 : 0.01f*c3;
            float* h0 = &Hs[(mrow+g)*HSTR + col];
            float* h1 = &Hs[(mrow+g+8)*HSTR + col];
            h0[0] = tf32rna(c0); h0[1] = tf32rna(c1);
            h1[0] = tf32rna(c2); h1[1] = tf32rna(c3);
        }
        __syncthreads();
    }

    // ---- stage 2: Y = H @ W2 + b2, N=128 in 2 chunks of 64, K=256 in 2 halves ----
    for (int nc2 = 0; nc2 < 2; nc2++) {
        float acc[4][4];
        #pragma unroll
        for (int jn = 0; jn < 4; jn++)
            acc[jn][0] = acc[jn][1] = acc[jn][2] = acc[jn][3] = 0.f;

        for (int kh = 0; kh < 2; kh++) {
            for (int i = tid; i < 128*16; i += 256) {
                int kk = i >> 4, j4 = i & 15;
                float4 wv = *reinterpret_cast<const float4*>(w2 + (size_t)(kh*128+kk)*CC + nc2*64 + j4*4);
                float* d = &Ws[kk*WSTR + j4*4];
                d[0] = tf32rna(wv.x); d[1] = tf32rna(wv.y);
                d[2] = tf32rna(wv.z); d[3] = tf32rna(wv.w);
            }
            __syncthreads();

            #pragma unroll
            for (int ks = 0; ks < 16; ks++) {
                uint32_t a[4];
                const float* h0 = &Hs[(mrow+g)*HSTR + kh*128 + ks*8];
                const float* h1 = h0 + 8*HSTR;
                a[0] = fbits(h0[t]); a[1] = fbits(h1[t]);
                a[2] = fbits(h0[t+4]); a[3] = fbits(h1[t+4]);
                #pragma unroll
                for (int jn = 0; jn < 4; jn++) {
                    const float* wr = &Ws[(ks*8+t)*WSTR + nhalf + jn*8 + g];
                    mma_tf32(acc[jn], a, fbits(wr[0]), fbits(wr[4*WSTR]));
                }
            }
            __syncthreads();
        }
        // bias + store Y into Xs region (X dead after stage1)
        #pragma unroll
        for (int jn = 0; jn < 4; jn++) {
            int col = nc2*64 + nhalf + jn*8 + 2*t;
            float* y0 = &Xs[(mrow+g)*XSTR + col];
            float* y1 = &Xs[(mrow+g+8)*XSTR + col];
            y0[0] = acc[jn][0] + Bs2[col];
            y0[1] = acc[jn][1] + Bs2[col+1];
            y1[0] = acc[jn][2] + Bs2[col];
            y1[1] = acc[jn][3] + Bs2[col+1];
        }
    }
    __syncthreads();

    // ---- epilogue: residual + output ----
    if (HAS_RES) {
        const float* rb = res + (size_t)gt0*CC;
        for (int i = tid; i < 64*CC; i += 256) {
            int tt = i >> 7, c = i & 127;
            Xs[tt*XSTR + c] += rb[i];
        }
        __syncthreads();
    }
    if (OUT_CHW) {
        float* ob = out + (size_t)b*CC*SS + s0;
        for (int i = tid; i < 64*CC; i += 256) {
            int c = i >> 6, tt = i & 63;
            ob[c*SS + tt] = Xs[tt*XSTR + c];
        }
    } else {
        float* ob = out + (size_t)gt0*CC;
        for (int i = tid; i < 64*CC; i += 256) {
            int tt = i >> 7, c = i & 127;
            ob[i] = Xs[tt*XSTR + c];
        }
    }
}

// ================= mma.sync tf32 flash attention (unchanged, known-good) =================
#define KVSTRIDE 36

__global__ __launch_bounds__(128) void attn_mma_kernel()
{
    __shared__ __align__(16) float Ks[64*KVSTRIDE];
    __shared__ __align__(16) float Vs[64*KVSTRIDE];

    const int tid  = threadIdx.x;
    const int wid  = tid >> 5;
    const int lane = tid & 31;
    const int g    = lane >> 2;
    const int t    = lane & 3;
    const int h = blockIdx.y, b = blockIdx.z;
    const int q0 = blockIdx.x * 64;

    const float* qg = g_qp + ((size_t)b*SS)*CC + h*DD;
    const float* kg = g_kp + ((size_t)b*SS)*CC + h*DD;
    const float* vg = g_vp + ((size_t)b*SS)*CC + h*DD;

    uint32_t qa[4][4];
    {
        const int r0 = q0 + wid*16 + g;
        const float* qrow0 = qg + (size_t)r0*CC;
        const float* qrow1 = qrow0 + 8*CC;
        #pragma unroll
        for (int kt = 0; kt < 4; kt++) {
            qa[kt][0] = __float_as_uint(qrow0[kt*8 + t]     * QS);
            qa[kt][1] = __float_as_uint(qrow1[kt*8 + t]     * QS);
            qa[kt][2] = __float_as_uint(qrow0[kt*8 + t + 4] * QS);
            qa[kt][3] = __float_as_uint(qrow1[kt*8 + t + 4] * QS);
        }
    }

    float O[4][4];
    #pragma unroll
    for (int j = 0; j < 4; j++)
        #pragma unroll
        for (int i = 0; i < 4; i++) O[j][i] = 0.f;
    float m0 = -1e30f, m1 = -1e30f, l0 = 0.f, l1 = 0.f;

    const int srcA = (lane & ~3) | (t >> 1);
    const int srcB = srcA + 2;

    for (int tile = 0; tile < SS/64; tile++) {
        #pragma unroll
        for (int r = 0; r < 4; r++) {
            int idx = tid + r*128;
            int row = idx >> 3, c4 = idx & 7;
            size_t goff = (size_t)(tile*64 + row)*CC + c4*4;
            float4 kv = *reinterpret_cast<const float4*>(kg + goff);
            float4 vv = *reinterpret_cast<const float4*>(vg + goff);
            *reinterpret_cast<float4*>(&Ks[row*KVSTRIDE + c4*4]) = kv;
            *reinterpret_cast<float4*>(&Vs[row*KVSTRIDE + c4*4]) = vv;
        }
        __syncthreads();

        float s[8][4];
        #pragma unroll
        for (int jn = 0; jn < 8; jn++) {
            s[jn][0] = s[jn][1] = s[jn][2] = s[jn][3] = 0.f;
            const float* krow = &Ks[(jn*8 + g)*KVSTRIDE];
            #pragma unroll
            for (int kt = 0; kt < 4; kt++) {
                uint32_t b0 = __float_as_uint(krow[kt*8 + t]);
                uint32_t b1 = __float_as_uint(krow[kt*8 + t + 4]);
                mma_tf32(s[jn], qa[kt], b0, b1);
            }
        }

        float mt0 = s[0][0], mt1 = s[0][2];
        #pragma unroll
        for (int jn = 0; jn < 8; jn++) {
            mt0 = fmaxf(mt0, fmaxf(s[jn][0], s[jn][1]));
            mt1 = fmaxf(mt1, fmaxf(s[jn][2], s[jn][3]));
        }
        mt0 = fmaxf(mt0, __shfl_xor_sync(0xffffffffu, mt0, 1));
        mt0 = fmaxf(mt0, __shfl_xor_sync(0xffffffffu, mt0, 2));
        mt1 = fmaxf(mt1, __shfl_xor_sync(0xffffffffu, mt1, 1));
        mt1 = fmaxf(mt1, __shfl_xor_sync(0xffffffffu, mt1, 2));
        const float mn0 = fmaxf(m0, mt0), mn1 = fmaxf(m1, mt1);
        const float corr0 = __expf(m0 - mn0), corr1 = __expf(m1 - mn1);
        m0 = mn0; m1 = mn1;
        float ls0 = 0.f, ls1 = 0.f;
        #pragma unroll
        for (int jn = 0; jn < 8; jn++) {
            s[jn][0] = __expf(s[jn][0] - mn0); ls0 += s[jn][0];
            s[jn][1] = __expf(s[jn][1] - mn0); ls0 += s[jn][1];
            s[jn][2] = __expf(s[jn][2] - mn1); ls1 += s[jn][2];
            s[jn][3] = __expf(s[jn][3] - mn1); ls1 += s[jn][3];
        }
        l0 = l0*corr0 + ls0;
        l1 = l1*corr1 + ls1;
        #pragma unroll
        for (int j = 0; j < 4; j++) {
            O[j][0] *= corr0; O[j][1] *= corr0;
            O[j][2] *= corr1; O[j][3] *= corr1;
        }

        #pragma unroll
        for (int kk = 0; kk < 8; kk++) {
            float v00 = __shfl_sync(0xffffffffu, s[kk][0], srcA);
            float v01 = __shfl_sync(0xffffffffu, s[kk][1], srcA);
            float v20 = __shfl_sync(0xffffffffu, s[kk][2], srcA);
            float v21 = __shfl_sync(0xffffffffu, s[kk][3], srcA);
            float w00 = __shfl_sync(0xffffffffu, s[kk][0], srcB);
            float w01 = __shfl_sync(0xffffffffu, s[kk][1], srcB);
            float w20 = __shfl_sync(0xffffffffu, s[kk][2], srcB);
            float w21 = __shfl_sync(0xffffffffu, s[kk][3], srcB);
            uint32_t pa[4];
            pa[0] = __float_as_uint((t & 1) ? v01 : v00);
            pa[1] = __float_as_uint((t & 1) ? v21 : v20);
            pa[2] = __float_as_uint((t & 1) ? w01 : w00);
            pa[3] = __float_as_uint((t & 1) ? w21 : w20);
            const float* vrow0 = &Vs[(kk*8 + t)*KVSTRIDE];
            const float* vrow1 = &Vs[(kk*8 + t + 4)*KVSTRIDE];
            #pragma unroll
            for (int jn = 0; jn < 4; jn++) {
                uint32_t b0 = __float_as_uint(vrow0[jn*8 + g]);
                uint32_t b1 = __float_as_uint(vrow1[jn*8 + g]);
                mma_tf32(O[jn], pa, b0, b1);
            }
        }
        __syncthreads();
    }

    l0 += __shfl_xor_sync(0xffffffffu, l0, 1);
    l0 += __shfl_xor_sync(0xffffffffu, l0, 2);
    l1 += __shfl_xor_sync(0xffffffffu, l1, 1);
    l1 += __shfl_xor_sync(0xffffffffu, l1, 2);
    const float inv0 = 1.0f / l0, inv1 = 1.0f / l1;
    const int r0 = q0 + wid*16 + g;
    float* o0 = g_x + ((size_t)b*SS + r0)*CC + h*DD;
    float* o1 = o0 + 8*CC;
    #pragma unroll
    for (int jn = 0; jn < 4; jn++) {
        float2 u0 = make_float2(O[jn][0]*inv0, O[jn][1]*inv0);
        float2 u1 = make_float2(O[jn][2]*inv1, O[jn][3]*inv1);
        *reinterpret_cast<float2*>(o0 + jn*8 + 2*t) = u0;
        *reinterpret_cast<float2*>(o1 + jn*8 + 2*t) = u1;
    }
}

// ---------------- launcher ----------------
extern "C" void kernel_launch(void* const* d_in, const int* in_sizes, int n_in,
                              void* d_out, int out_size)
{
    (void)in_sizes; (void)n_in; (void)out_size;
    const float* q      = (const float*)d_in[0];
    const float* k      = (const float*)d_in[1];
    const float* v      = (const float*)d_in[2];
    const float* ln_q_g = (const float*)d_in[3];
    const float* ln_q_b = (const float*)d_in[4];
    const float* wq1    = (const float*)d_in[5];
    const float* bq1    = (const float*)d_in[6];
    const float* wq2    = (const float*)d_in[7];
    const float* bq2    = (const float*)d_in[8];
    const float* ln_k_g = (const float*)d_in[9];
    const float* ln_k_b = (const float*)d_in[10];
    const float* wk1    = (const float*)d_in[11];
    const float* bk1    = (const float*)d_in[12];
    const float* wk2    = (const float*)d_in[13];
    const float* bk2    = (const float*)d_in[14];
    const float* ln_v_g = (const float*)d_in[15];
    const float* ln_v_b = (const float*)d_in[16];
    const float* wv1    = (const float*)d_in[17];
    const float* bv1    = (const float*)d_in[18];
    const float* wv2    = (const float*)d_in[19];
    const float* bv2    = (const float*)d_in[20];
    const float* m1_w1  = (const float*)d_in[21];
    const float* m1_b1  = (const float*)d_in[22];
    const float* m1_w2  = (const float*)d_in[23];
    const float* m1_b2  = (const float*)d_in[24];
    const float* m2_w1  = (const float*)d_in[25];
    const float* m2_b1  = (const float*)d_in[26];
    const float* m2_w2  = (const float*)d_in[27];
    const float* m2_b2  = (const float*)d_in[28];
    float* out = (float*)d_out;

    cudaFuncSetAttribute(proj_tc_kernel<0,false,false>,
                         cudaFuncAttributeMaxDynamicSharedMemorySize, PROJ_SMEM_BYTES);
    cudaFuncSetAttribute(proj_tc_kernel<1,true,false>,
                         cudaFuncAttributeMaxDynamicSharedMemorySize, PROJ_SMEM_BYTES);
    cudaFuncSetAttribute(proj_tc_kernel<1,true,true>,
                         cudaFuncAttributeMaxDynamicSharedMemorySize, PROJ_SMEM_BYTES);

    const int nblk = (BB*SS)/64;  // 128

    // q/k/v projections: CHW in + LN, token-major out to scratch 0/1/2
    proj_tc_kernel<0,false,false><<<nblk, 256, PROJ_SMEM_BYTES>>>(
        q, -1, ln_q_g, ln_q_b, wq1, bq1, wq2, bq2, nullptr, -1, nullptr, 0);
    proj_tc_kernel<0,false,false><<<nblk, 256, PROJ_SMEM_BYTES>>>(
        k, -1, ln_k_g, ln_k_b, wk1, bk1, wk2, bk2, nullptr, -1, nullptr, 1);
    proj_tc_kernel<0,false,false><<<nblk, 256, PROJ_SMEM_BYTES>>>(
        v, -1, ln_v_g, ln_v_b, wv1, bv1, wv2, bv2, nullptr, -1, nullptr, 2);

    // mma.sync tf32 flash attention: g_qp/g_kp/g_vp -> g_x
    attn_mma_kernel<<<dim3(SS/64, NH, BB), 128>>>();

    // rs1 = vp + mlp1(x)
    proj_tc_kernel<1,true,false><<<nblk, 256, PROJ_SMEM_BYTES>>>(
        nullptr, 3, nullptr, nullptr, m1_w1, m1_b1, m1_w2, m1_b2, nullptr, 2, nullptr, 4);

    // rs2 = rs1 + mlp2(rs1), CHW out
    proj_tc_kernel<1,true,true><<<nblk, 256, PROJ_SMEM_BYTES>>>(
        nullptr, 4, nullptr, nullptr, m2_w1, m2_b1, m2_w2, m2_b2, nullptr, 4, out, -1);
}

// round 5
// speedup vs baseline: 3.9269x; 1.2424x over previous
#include <cuda_runtime.h>
#include <math.h>
#include <stdint.h>

#define BB 2
#define CC 128
#define HH 256      // 2*C
#define SS 4096     // 64*64 tokens
#define NH 4
#define DD 32       // head dim

#define QS 0.1767766952966369f   // 1/sqrt(32)
#define QS2 (QS * 1.4426950408889634f)   // fold log2(e) for ex2-domain softmax

// ---------------- scratch (no allocation allowed) ----------------
__device__ float g_qp[BB*SS*CC];
__device__ float g_kp[BB*SS*CC];
__device__ float g_vp[BB*SS*CC];
__device__ float g_x [BB*SS*CC];
__device__ float g_r1[BB*SS*CC];

__device__ __forceinline__ const float* sel_in(int sel, const float* ext) {
    switch (sel) {
        case 0: return g_qp; case 1: return g_kp; case 2: return g_vp;
        case 3: return g_x;  case 4: return g_r1;
    }
    return ext;
}
__device__ __forceinline__ float* sel_out(int sel, float* ext) {
    switch (sel) {
        case 0: return g_qp; case 1: return g_kp; case 2: return g_vp;
        case 3: return g_x;  case 4: return g_r1;
    }
    return ext;
}

// tf32 mma m16n8k8 row.col: D += A*B
__device__ __forceinline__ void mma_tf32(float* c, const uint32_t* a, uint32_t b0, uint32_t b1) {
    asm volatile(
        "mma.sync.aligned.m16n8k8.row.col.f32.tf32.tf32.f32 "
        "{%0,%1,%2,%3}, {%4,%5,%6,%7}, {%8,%9}, {%0,%1,%2,%3};"
        : "+f"(c[0]), "+f"(c[1]), "+f"(c[2]), "+f"(c[3])
        : "r"(a[0]), "r"(a[1]), "r"(a[2]), "r"(a[3]), "r"(b0), "r"(b1));
}
__device__ __forceinline__ float tf32rna(float x) {
    uint32_t r;
    asm("cvt.rna.tf32.f32 %0, %1;" : "=r"(r) : "f"(x));
    return __uint_as_float(r);
}
__device__ __forceinline__ uint32_t fbits(float x) { return __float_as_uint(x); }
__device__ __forceinline__ float fexp2(float x) {
    float r;
    asm("ex2.approx.f32 %0, %1;" : "=f"(r) : "f"(x));
    return r;
}

// ================= mma.sync tf32 flash attention (BM=128/CTA, 2 mfrags/warp) =================
// grid (32, 4, 2), 128 threads. BN=64 keys/tile, cp.async double buffer.
#define KVSTRIDE 36

__global__ __launch_bounds__(128, 2) void attn_mma_kernel()
{
    __shared__ __align__(16) float Ks[2][64*KVSTRIDE];
    __shared__ __align__(16) float Vs[2][64*KVSTRIDE];

    const int tid  = threadIdx.x;
    const int wid  = tid >> 5;
    const int lane = tid & 31;
    const int g    = lane >> 2;
    const int t    = lane & 3;
    const int h = blockIdx.y, b = blockIdx.z;
    const int q0 = blockIdx.x * 128;

    const float* qg = g_qp + ((size_t)b*SS)*CC + h*DD;
    const float* kg = g_kp + ((size_t)b*SS)*CC + h*DD;
    const float* vg = g_vp + ((size_t)b*SS)*CC + h*DD;

    // ---- Q A-fragments for both mfrags, scaled by QS*log2e ----
    uint32_t qa[2][4][4];
    #pragma unroll
    for (int mf = 0; mf < 2; mf++) {
        const int r0 = q0 + wid*32 + mf*16 + g;
        const float* qrow0 = qg + (size_t)r0*CC;
        const float* qrow1 = qrow0 + 8*CC;
        #pragma unroll
        for (int kt = 0; kt < 4; kt++) {
            qa[mf][kt][0] = fbits(qrow0[kt*8 + t]     * QS2);
            qa[mf][kt][1] = fbits(qrow1[kt*8 + t]     * QS2);
            qa[mf][kt][2] = fbits(qrow0[kt*8 + t + 4] * QS2);
            qa[mf][kt][3] = fbits(qrow1[kt*8 + t + 4] * QS2);
        }
    }

    float O[2][4][4];
    float m[2][2], l[2][2];
    #pragma unroll
    for (int mf = 0; mf < 2; mf++) {
        #pragma unroll
        for (int j = 0; j < 4; j++)
            #pragma unroll
            for (int i = 0; i < 4; i++) O[mf][j][i] = 0.f;
        m[mf][0] = m[mf][1] = -1e30f;
        l[mf][0] = l[mf][1] = 0.f;
    }

    const int srcA = (lane & ~3) | (t >> 1);
    const int srcB = srcA + 2;

    // cp.async tile loader: 64 rows x 32 floats per tensor, 4x16B per thread each
    auto cp_tile = [&](int tile, int buf) {
        #pragma unroll
        for (int r = 0; r < 4; r++) {
            int idx = tid + r*128;
            int row = idx >> 3, c4 = idx & 7;
            size_t goff = (size_t)(tile*64 + row)*CC + c4*4;
            uint32_t kd = (uint32_t)__cvta_generic_to_shared(&Ks[buf][row*KVSTRIDE + c4*4]);
            uint32_t vd = (uint32_t)__cvta_generic_to_shared(&Vs[buf][row*KVSTRIDE + c4*4]);
            asm volatile("cp.async.ca.shared.global [%0], [%1], 16;" :: "r"(kd), "l"(kg + goff));
            asm volatile("cp.async.ca.shared.global [%0], [%1], 16;" :: "r"(vd), "l"(vg + goff));
        }
        asm volatile("cp.async.commit_group;" ::: "memory");
    };

    cp_tile(0, 0);

    for (int tile = 0; tile < SS/64; tile++) {
        const int buf = tile & 1;
        if (tile + 1 < SS/64) {
            cp_tile(tile + 1, buf ^ 1);
            asm volatile("cp.async.wait_group 1;" ::: "memory");
        } else {
            asm volatile("cp.async.wait_group 0;" ::: "memory");
        }
        __syncthreads();

        // ---- S = Q @ K^T : shared B loads serve both mfrags ----
        float s[2][8][4];
        #pragma unroll
        for (int jn = 0; jn < 8; jn++) {
            #pragma unroll
            for (int mf = 0; mf < 2; mf++)
                s[mf][jn][0] = s[mf][jn][1] = s[mf][jn][2] = s[mf][jn][3] = 0.f;
            const float* krow = &Ks[buf][(jn*8 + g)*KVSTRIDE];
            #pragma unroll
            for (int kt = 0; kt < 4; kt++) {
                uint32_t b0 = fbits(krow[kt*8 + t]);
                uint32_t b1 = fbits(krow[kt*8 + t + 4]);
                mma_tf32(s[0][jn], qa[0][kt], b0, b1);
                mma_tf32(s[1][jn], qa[1][kt], b0, b1);
            }
        }

        // ---- online softmax (log2 domain) ----
        float corr[2][2];
        #pragma unroll
        for (int mf = 0; mf < 2; mf++) {
            float mt0 = s[mf][0][0], mt1 = s[mf][0][2];
            #pragma unroll
            for (int jn = 0; jn < 8; jn++) {
                mt0 = fmaxf(mt0, fmaxf(s[mf][jn][0], s[mf][jn][1]));
                mt1 = fmaxf(mt1, fmaxf(s[mf][jn][2], s[mf][jn][3]));
            }
            mt0 = fmaxf(mt0, __shfl_xor_sync(0xffffffffu, mt0, 1));
            mt0 = fmaxf(mt0, __shfl_xor_sync(0xffffffffu, mt0, 2));
            mt1 = fmaxf(mt1, __shfl_xor_sync(0xffffffffu, mt1, 1));
            mt1 = fmaxf(mt1, __shfl_xor_sync(0xffffffffu, mt1, 2));
            const float mn0 = fmaxf(m[mf][0], mt0), mn1 = fmaxf(m[mf][1], mt1);
            corr[mf][0] = fexp2(m[mf][0] - mn0);
            corr[mf][1] = fexp2(m[mf][1] - mn1);
            m[mf][0] = mn0; m[mf][1] = mn1;
            float ls0 = 0.f, ls1 = 0.f;
            #pragma unroll
            for (int jn = 0; jn < 8; jn++) {
                s[mf][jn][0] = fexp2(s[mf][jn][0] - mn0); ls0 += s[mf][jn][0];
                s[mf][jn][1] = fexp2(s[mf][jn][1] - mn0); ls0 += s[mf][jn][1];
                s[mf][jn][2] = fexp2(s[mf][jn][2] - mn1); ls1 += s[mf][jn][2];
                s[mf][jn][3] = fexp2(s[mf][jn][3] - mn1); ls1 += s[mf][jn][3];
            }
            l[mf][0] = l[mf][0]*corr[mf][0] + ls0;
            l[mf][1] = l[mf][1]*corr[mf][1] + ls1;
            #pragma unroll
            for (int j = 0; j < 4; j++) {
                O[mf][j][0] *= corr[mf][0]; O[mf][j][1] *= corr[mf][0];
                O[mf][j][2] *= corr[mf][1]; O[mf][j][3] *= corr[mf][1];
            }
        }

        // ---- O += P @ V : V B loads shared across mfrags ----
        #pragma unroll
        for (int kk = 0; kk < 8; kk++) {
            uint32_t pa[2][4];
            #pragma unroll
            for (int mf = 0; mf < 2; mf++) {
                float v00 = __shfl_sync(0xffffffffu, s[mf][kk][0], srcA);
                float v01 = __shfl_sync(0xffffffffu, s[mf][kk][1], srcA);
                float v20 = __shfl_sync(0xffffffffu, s[mf][kk][2], srcA);
                float v21 = __shfl_sync(0xffffffffu, s[mf][kk][3], srcA);
                float w00 = __shfl_sync(0xffffffffu, s[mf][kk][0], srcB);
                float w01 = __shfl_sync(0xffffffffu, s[mf][kk][1], srcB);
                float w20 = __shfl_sync(0xffffffffu, s[mf][kk][2], srcB);
                float w21 = __shfl_sync(0xffffffffu, s[mf][kk][3], srcB);
                pa[mf][0] = fbits((t & 1) ? v01 : v00);
                pa[mf][1] = fbits((t & 1) ? v21 : v20);
                pa[mf][2] = fbits((t & 1) ? w01 : w00);
                pa[mf][3] = fbits((t & 1) ? w21 : w20);
            }
            const float* vrow0 = &Vs[buf][(kk*8 + t)*KVSTRIDE];
            const float* vrow1 = &Vs[buf][(kk*8 + t + 4)*KVSTRIDE];
            #pragma unroll
            for (int jn = 0; jn < 4; jn++) {
                uint32_t b0 = fbits(vrow0[jn*8 + g]);
                uint32_t b1 = fbits(vrow1[jn*8 + g]);
                mma_tf32(O[0][jn], pa[0], b0, b1);
                mma_tf32(O[1][jn], pa[1], b0, b1);
            }
        }
        __syncthreads();
    }

    // ---- epilogue ----
    #pragma unroll
    for (int mf = 0; mf < 2; mf++) {
        float l0 = l[mf][0], l1 = l[mf][1];
        l0 += __shfl_xor_sync(0xffffffffu, l0, 1);
        l0 += __shfl_xor_sync(0xffffffffu, l0, 2);
        l1 += __shfl_xor_sync(0xffffffffu, l1, 1);
        l1 += __shfl_xor_sync(0xffffffffu, l1, 2);
        const float inv0 = 1.0f / l0, inv1 = 1.0f / l1;
        const int r0 = q0 + wid*32 + mf*16 + g;
        float* o0 = g_x + ((size_t)b*SS + r0)*CC + h*DD;
        float* o1 = o0 + 8*CC;
        #pragma unroll
        for (int jn = 0; jn < 4; jn++) {
            float2 u0 = make_float2(O[mf][jn][0]*inv0, O[mf][jn][1]*inv0);
            float2 u1 = make_float2(O[mf][jn][2]*inv1, O[mf][jn][3]*inv1);
            *reinterpret_cast<float2*>(o0 + jn*8 + 2*t) = u0;
            *reinterpret_cast<float2*>(o1 + jn*8 + 2*t) = u1;
        }
    }
}

// ================= tensor-core fused projection (unchanged, known-good) =================
#define XSTR 132
#define HSTR 260
#define WSTR 72
#define PROJ_SMEM_FLOATS (64*XSTR + 64*HSTR + 128*WSTR + 256 + 128 + 128 + 128 + 64 + 64)
#define PROJ_SMEM_BYTES (PROJ_SMEM_FLOATS*4)

template<int INMODE /*0=CHW+LN, 1=token-major*/, bool HAS_RES, bool OUT_CHW>
__global__ __launch_bounds__(256)
void proj_tc_kernel(const float* __restrict__ in_ext, int in_sel,
                    const float* __restrict__ gamma, const float* __restrict__ beta,
                    const float* __restrict__ w1, const float* __restrict__ b1,
                    const float* __restrict__ w2, const float* __restrict__ b2,
                    const float* __restrict__ res_ext, int res_sel,
                    float* __restrict__ out_ext, int out_sel)
{
    extern __shared__ float sm[];
    float* Xs  = sm;
    float* Hs  = Xs + 64*XSTR;
    float* Ws  = Hs + 64*HSTR;
    float* Bs1 = Ws + 128*WSTR;
    float* Bs2 = Bs1 + 256;
    float* Gs  = Bs2 + 128;
    float* Bts = Gs + 128;
    float* MUs = Bts + 128;
    float* RIs = MUs + 64;

    const float* in  = sel_in(in_sel, in_ext);
    const float* res = HAS_RES ? sel_in(res_sel, res_ext) : nullptr;
    float*       out = sel_out(out_sel, out_ext);

    const int tid  = threadIdx.x;
    const int wid  = tid >> 5;
    const int lane = tid & 31;
    const int g    = lane >> 2;
    const int t    = lane & 3;
    const int mrow  = (wid & 3) * 16;
    const int nhalf = (wid >> 2) * 32;

    const int gt0 = blockIdx.x * 64;
    const int b   = gt0 >> 12;
    const int s0  = gt0 & (SS - 1);

    if (tid < 256) Bs1[tid] = b1[tid];
    if (tid < 128) Bs2[tid] = b2[tid];
    if (INMODE == 0 && tid < 128) { Gs[tid] = gamma[tid]; Bts[tid] = beta[tid]; }

    if (INMODE == 0) {
        const float* base = in + (size_t)b*CC*SS + s0;
        for (int i = tid; i < 64*CC; i += 256) {
            int c = i >> 6, tt = i & 63;
            Xs[tt*XSTR + c] = base[c*SS + tt];
        }
    } else {
        const float* base = in + (size_t)gt0*CC;
        for (int i = tid; i < 64*CC; i += 256) {
            int tt = i >> 7, c = i & 127;
            Xs[tt*XSTR + c] = tf32rna(base[i]);
        }
    }
    __syncthreads();

    if (INMODE == 0) {
        if (tid < 64) {
            float s = 0.f, s2 = 0.f;
            const float* xr = &Xs[tid*XSTR];
            for (int c = 0; c < CC; c++) { float v = xr[c]; s += v; s2 += v*v; }
            float mu = s * (1.0f/CC);
            float var = s2 * (1.0f/CC) - mu*mu;
            MUs[tid] = mu;
            RIs[tid] = rsqrtf(var + 1e-5f);
        }
        __syncthreads();
        for (int i = tid; i < 64*CC; i += 256) {
            int tt = i >> 7, c = i & 127;
            float v = Xs[tt*XSTR + c];
            v = (v - MUs[tt]) * RIs[tt] * Gs[c] + Bts[c];
            Xs[tt*XSTR + c] = tf32rna(v);
        }
        __syncthreads();
    }

    for (int nc = 0; nc < 4; nc++) {
        for (int i = tid; i < 128*16; i += 256) {
            int kk = i >> 4, j4 = i & 15;
            float4 wv = *reinterpret_cast<const float4*>(w1 + kk*HH + nc*64 + j4*4);
            float* d = &Ws[kk*WSTR + j4*4];
            d[0] = tf32rna(wv.x); d[1] = tf32rna(wv.y);
            d[2] = tf32rna(wv.z); d[3] = tf32rna(wv.w);
        }
        __syncthreads();

        float acc[4][4];
        #pragma unroll
        for (int jn = 0; jn < 4; jn++)
            acc[jn][0] = acc[jn][1] = acc[jn][2] = acc[jn][3] = 0.f;

        #pragma unroll
        for (int ks = 0; ks < 16; ks++) {
            uint32_t a[4];
            const float* x0 = &Xs[(mrow+g)*XSTR + ks*8];
            const float* x1 = x0 + 8*XSTR;
            a[0] = fbits(x0[t]); a[1] = fbits(x1[t]);
            a[2] = fbits(x0[t+4]); a[3] = fbits(x1[t+4]);
            #pragma unroll
            for (int jn = 0; jn < 4; jn++) {
                const float* wr = &Ws[(ks*8+t)*WSTR + nhalf + jn*8 + g];
                mma_tf32(acc[jn], a, fbits(wr[0]), fbits(wr[4*WSTR]));
            }
        }
        #pragma unroll
        for (int jn = 0; jn < 4; jn++) {
            int col = nc*64 + nhalf + jn*8 + 2*t;
            float c0 = acc[jn][0] + Bs1[col];
            float c1 = acc[jn][1] + Bs1[col+1];
            float c2 = acc[jn][2] + Bs1[col];
            float c3 = acc[jn][3] + Bs1[col+1];
            c0 = (c0 > 0.f) ? c0 : 0.01f*c0;
            c1 = (c1 > 0.f) ? c1 : 0.01f*c1;
            c2 = (c2 > 0.f) ? c2 : 0.01f*c2;
            c3 = (c3 > 0.f) ? c3 : 0.01f*c3;
            float* h0 = &Hs[(mrow+g)*HSTR + col];
            float* h1 = &Hs[(mrow+g+8)*HSTR + col];
            h0[0] = tf32rna(c0); h0[1] = tf32rna(c1);
            h1[0] = tf32rna(c2); h1[1] = tf32rna(c3);
        }
        __syncthreads();
    }

    for (int nc2 = 0; nc2 < 2; nc2++) {
        float acc[4][4];
        #pragma unroll
        for (int jn = 0; jn < 4; jn++)
            acc[jn][0] = acc[jn][1] = acc[jn][2] = acc[jn][3] = 0.f;

        for (int kh = 0; kh < 2; kh++) {
            for (int i = tid; i < 128*16; i += 256) {
                int kk = i >> 4, j4 = i & 15;
                float4 wv = *reinterpret_cast<const float4*>(w2 + (size_t)(kh*128+kk)*CC + nc2*64 + j4*4);
                float* d = &Ws[kk*WSTR + j4*4];
                d[0] = tf32rna(wv.x); d[1] = tf32rna(wv.y);
                d[2] = tf32rna(wv.z); d[3] = tf32rna(wv.w);
            }
            __syncthreads();

            #pragma unroll
            for (int ks = 0; ks < 16; ks++) {
                uint32_t a[4];
                const float* h0 = &Hs[(mrow+g)*HSTR + kh*128 + ks*8];
                const float* h1 = h0 + 8*HSTR;
                a[0] = fbits(h0[t]); a[1] = fbits(h1[t]);
                a[2] = fbits(h0[t+4]); a[3] = fbits(h1[t+4]);
                #pragma unroll
                for (int jn = 0; jn < 4; jn++) {
                    const float* wr = &Ws[(ks*8+t)*WSTR + nhalf + jn*8 + g];
                    mma_tf32(acc[jn], a, fbits(wr[0]), fbits(wr[4*WSTR]));
                }
            }
            __syncthreads();
        }
        #pragma unroll
        for (int jn = 0; jn < 4; jn++) {
            int col = nc2*64 + nhalf + jn*8 + 2*t;
            float* y0 = &Xs[(mrow+g)*XSTR + col];
            float* y1 = &Xs[(mrow+g+8)*XSTR + col];
            y0[0] = acc[jn][0] + Bs2[col];
            y0[1] = acc[jn][1] + Bs2[col+1];
            y1[0] = acc[jn][2] + Bs2[col];
            y1[1] = acc[jn][3] + Bs2[col+1];
        }
    }
    __syncthreads();

    if (HAS_RES) {
        const float* rb = res + (size_t)gt0*CC;
        for (int i = tid; i < 64*CC; i += 256) {
            int tt = i >> 7, c = i & 127;
            Xs[tt*XSTR + c] += rb[i];
        }
        __syncthreads();
    }
    if (OUT_CHW) {
        float* ob = out + (size_t)b*CC*SS + s0;
        for (int i = tid; i < 64*CC; i += 256) {
            int c = i >> 6, tt = i & 63;
            ob[c*SS + tt] = Xs[tt*XSTR + c];
        }
    } else {
        float* ob = out + (size_t)gt0*CC;
        for (int i = tid; i < 64*CC; i += 256) {
            int tt = i >> 7, c = i & 127;
            ob[i] = Xs[tt*XSTR + c];
        }
    }
}

// ---------------- launcher ----------------
extern "C" void kernel_launch(void* const* d_in, const int* in_sizes, int n_in,
                              void* d_out, int out_size)
{
    (void)in_sizes; (void)n_in; (void)out_size;
    const float* q      = (const float*)d_in[0];
    const float* k      = (const float*)d_in[1];
    const float* v      = (const float*)d_in[2];
    const float* ln_q_g = (const float*)d_in[3];
    const float* ln_q_b = (const float*)d_in[4];
    const float* wq1    = (const float*)d_in[5];
    const float* bq1    = (const float*)d_in[6];
    const float* wq2    = (const float*)d_in[7];
    const float* bq2    = (const float*)d_in[8];
    const float* ln_k_g = (const float*)d_in[9];
    const float* ln_k_b = (const float*)d_in[10];
    const float* wk1    = (const float*)d_in[11];
    const float* bk1    = (const float*)d_in[12];
    const float* wk2    = (const float*)d_in[13];
    const float* bk2    = (const float*)d_in[14];
    const float* ln_v_g = (const float*)d_in[15];
    const float* ln_v_b = (const float*)d_in[16];
    const float* wv1    = (const float*)d_in[17];
    const float* bv1    = (const float*)d_in[18];
    const float* wv2    = (const float*)d_in[19];
    const float* bv2    = (const float*)d_in[20];
    const float* m1_w1  = (const float*)d_in[21];
    const float* m1_b1  = (const float*)d_in[22];
    const float* m1_w2  = (const float*)d_in[23];
    const float* m1_b2  = (const float*)d_in[24];
    const float* m2_w1  = (const float*)d_in[25];
    const float* m2_b1  = (const float*)d_in[26];
    const float* m2_w2  = (const float*)d_in[27];
    const float* m2_b2  = (const float*)d_in[28];
    float* out = (float*)d_out;

    cudaFuncSetAttribute(proj_tc_kernel<0,false,false>,
                         cudaFuncAttributeMaxDynamicSharedMemorySize, PROJ_SMEM_BYTES);
    cudaFuncSetAttribute(proj_tc_kernel<1,true,false>,
                         cudaFuncAttributeMaxDynamicSharedMemorySize, PROJ_SMEM_BYTES);
    cudaFuncSetAttribute(proj_tc_kernel<1,true,true>,
                         cudaFuncAttributeMaxDynamicSharedMemorySize, PROJ_SMEM_BYTES);

    const int nblk = (BB*SS)/64;  // 128

    proj_tc_kernel<0,false,false><<<nblk, 256, PROJ_SMEM_BYTES>>>(
        q, -1, ln_q_g, ln_q_b, wq1, bq1, wq2, bq2, nullptr, -1, nullptr, 0);
    proj_tc_kernel<0,false,false><<<nblk, 256, PROJ_SMEM_BYTES>>>(
        k, -1, ln_k_g, ln_k_b, wk1, bk1, wk2, bk2, nullptr, -1, nullptr, 1);
    proj_tc_kernel<0,false,false><<<nblk, 256, PROJ_SMEM_BYTES>>>(
        v, -1, ln_v_g, ln_v_b, wv1, bv1, wv2, bv2, nullptr, -1, nullptr, 2);

    attn_mma_kernel<<<dim3(SS/128, NH, BB), 128>>>();

    proj_tc_kernel<1,true,false><<<nblk, 256, PROJ_SMEM_BYTES>>>(
        nullptr, 3, nullptr, nullptr, m1_w1, m1_b1, m1_w2, m1_b2, nullptr, 2, nullptr, 4);

    proj_tc_kernel<1,true,true><<<nblk, 256, PROJ_SMEM_BYTES>>>(
        nullptr, 4, nullptr, nullptr, m2_w1, m2_b1, m2_w2, m2_b2, nullptr, 4, out, -1);
}

// round 6
// speedup vs baseline: 4.1750x; 1.0632x over previous
#include <cuda_runtime.h>
#include <math.h>
#include <stdint.h>

#define BB 2
#define CC 128
#define HH 256      // 2*C
#define SS 4096     // 64*64 tokens
#define NH 4
#define DD 32       // head dim

#define QS 0.1767766952966369f   // 1/sqrt(32)
#define QS2 (QS * 1.4426950408889634f)   // fold log2(e) for ex2-domain softmax

// ---------------- scratch (no allocation allowed) ----------------
__device__ float g_qp[BB*SS*CC];
__device__ float g_kp[BB*SS*CC];
__device__ float g_vp[BB*SS*CC];
__device__ float g_x [BB*SS*CC];
__device__ float g_r1[BB*SS*CC];

__device__ __forceinline__ const float* sel_in(int sel, const float* ext) {
    switch (sel) {
        case 0: return g_qp; case 1: return g_kp; case 2: return g_vp;
        case 3: return g_x;  case 4: return g_r1;
    }
    return ext;
}
__device__ __forceinline__ float* sel_out(int sel, float* ext) {
    switch (sel) {
        case 0: return g_qp; case 1: return g_kp; case 2: return g_vp;
        case 3: return g_x;  case 4: return g_r1;
    }
    return ext;
}

// tf32 mma m16n8k8 row.col: D += A*B
__device__ __forceinline__ void mma_tf32(float* c, const uint32_t* a, uint32_t b0, uint32_t b1) {
    asm volatile(
        "mma.sync.aligned.m16n8k8.row.col.f32.tf32.tf32.f32 "
        "{%0,%1,%2,%3}, {%4,%5,%6,%7}, {%8,%9}, {%0,%1,%2,%3};"
        : "+f"(c[0]), "+f"(c[1]), "+f"(c[2]), "+f"(c[3])
        : "r"(a[0]), "r"(a[1]), "r"(a[2]), "r"(a[3]), "r"(b0), "r"(b1));
}
__device__ __forceinline__ float tf32rna(float x) {
    uint32_t r;
    asm("cvt.rna.tf32.f32 %0, %1;" : "=r"(r) : "f"(x));
    return __uint_as_float(r);
}
__device__ __forceinline__ uint32_t fbits(float x) { return __float_as_uint(x); }
__device__ __forceinline__ float fexp2(float x) {
    float r;
    asm("ex2.approx.f32 %0, %1;" : "=f"(r) : "f"(x));
    return r;
}

// ================= restructured tensor-core fused projection =================
// (LN) -> Linear(128,256) -> LeakyReLU -> Linear(256,128) (+res)
// Stage1/stage2 interleaved per 64-col hidden chunk; stage2 accum in registers.
// smem ~89KB -> 2 CTAs/SM. CTA: 64 tokens, 256 threads (4 m-groups x 2 n-groups).
#define XSTR 132
#define HCSTR 68
#define W1STR 72
#define W2STR 132
// floats: X 64*132=8448, Hc 64*68=4352, W max(128*72, 64*132)=9216,
// b1 256, b2 128, g 128, bt 128, mu 64, ri 64 -> 22784 floats
#define PROJ_SMEM_FLOATS (64*XSTR + 64*HCSTR + 9216 + 256 + 128 + 128 + 128 + 64 + 64)
#define PROJ_SMEM_BYTES (PROJ_SMEM_FLOATS*4)

struct ProjSet { const float *gam, *bet, *w1, *b1, *w2, *b2; };
struct QKVArgs { const float* in[3]; ProjSet ps[3]; };

// Shared body. INMODE 0: CHW input + LN. INMODE 1: token-major input, no LN.
template<int INMODE, bool HAS_RES, bool OUT_CHW>
__device__ __forceinline__ void proj_body(
    const float* __restrict__ in, const float* __restrict__ gamma, const float* __restrict__ beta,
    const float* __restrict__ w1, const float* __restrict__ b1,
    const float* __restrict__ w2, const float* __restrict__ b2,
    const float* __restrict__ res, float* __restrict__ out, int bx)
{
    extern __shared__ float sm[];
    float* Xs  = sm;                    // [64][132]
    float* Hcs = Xs + 64*XSTR;          // [64][68]
    float* Ws  = Hcs + 64*HCSTR;        // [128][72] or [64][132]
    float* Bs1 = Ws + 9216;             // [256]
    float* Bs2 = Bs1 + 256;             // [128]
    float* Gs  = Bs2 + 128;             // [128]
    float* Bts = Gs + 128;              // [128]
    float* MUs = Bts + 128;             // [64]
    float* RIs = MUs + 64;              // [64]

    const int tid  = threadIdx.x;
    const int wid  = tid >> 5;
    const int lane = tid & 31;
    const int g    = lane >> 2;
    const int t    = lane & 3;
    const int mrow  = (wid & 3) * 16;
    const int nhalf = (wid >> 2) * 32;

    const int gt0 = bx * 64;
    const int b   = gt0 >> 12;
    const int s0  = gt0 & (SS - 1);

    if (tid < 256) Bs1[tid] = b1[tid];
    if (tid < 128) Bs2[tid] = b2[tid];
    if (INMODE == 0 && tid < 128) { Gs[tid] = gamma[tid]; Bts[tid] = beta[tid]; }

    // ---- load X tile ----
    if (INMODE == 0) {
        const float* base = in + (size_t)b*CC*SS + s0;
        for (int i = tid; i < 64*CC; i += 256) {
            int c = i >> 6, tt = i & 63;
            Xs[tt*XSTR + c] = base[c*SS + tt];
        }
    } else {
        const float* base = in + (size_t)gt0*CC;
        for (int i = tid; i < 64*CC; i += 256) {
            int tt = i >> 7, c = i & 127;
            Xs[tt*XSTR + c] = tf32rna(base[i]);
        }
    }
    __syncthreads();

    if (INMODE == 0) {
        if (tid < 64) {
            float s = 0.f, s2 = 0.f;
            const float* xr = &Xs[tid*XSTR];
            for (int c = 0; c < CC; c++) { float v = xr[c]; s += v; s2 += v*v; }
            float mu = s * (1.0f/CC);
            float var = s2 * (1.0f/CC) - mu*mu;
            MUs[tid] = mu;
            RIs[tid] = rsqrtf(var + 1e-5f);
        }
        __syncthreads();
        for (int i = tid; i < 64*CC; i += 256) {
            int tt = i >> 7, c = i & 127;
            float v = Xs[tt*XSTR + c];
            v = (v - MUs[tt]) * RIs[tt] * Gs[c] + Bts[c];
            Xs[tt*XSTR + c] = tf32rna(v);
        }
        __syncthreads();
    }

    // stage-2 accumulators live across all hidden chunks
    float acc2[2][4][4];
    #pragma unroll
    for (int n2 = 0; n2 < 2; n2++)
        #pragma unroll
        for (int jn = 0; jn < 4; jn++)
            acc2[n2][jn][0] = acc2[n2][jn][1] = acc2[n2][jn][2] = acc2[n2][jn][3] = 0.f;

    for (int hc = 0; hc < 4; hc++) {
        // ---- load W1 chunk [128 k][64 n] ----
        for (int i = tid; i < 128*16; i += 256) {
            int kk = i >> 4, j4 = i & 15;
            float4 wv = *reinterpret_cast<const float4*>(w1 + kk*HH + hc*64 + j4*4);
            float* d = &Ws[kk*W1STR + j4*4];
            d[0] = tf32rna(wv.x); d[1] = tf32rna(wv.y);
            d[2] = tf32rna(wv.z); d[3] = tf32rna(wv.w);
        }
        __syncthreads();

        // ---- stage 1: Hc = leaky(X @ W1c + b1c) ----
        float acc[4][4];
        #pragma unroll
        for (int jn = 0; jn < 4; jn++)
            acc[jn][0] = acc[jn][1] = acc[jn][2] = acc[jn][3] = 0.f;
        #pragma unroll
        for (int ks = 0; ks < 16; ks++) {
            uint32_t a[4];
            const float* x0 = &Xs[(mrow+g)*XSTR + ks*8];
            const float* x1 = x0 + 8*XSTR;
            a[0] = fbits(x0[t]); a[1] = fbits(x1[t]);
            a[2] = fbits(x0[t+4]); a[3] = fbits(x1[t+4]);
            #pragma unroll
            for (int jn = 0; jn < 4; jn++) {
                const float* wr = &Ws[(ks*8+t)*W1STR + nhalf + jn*8 + g];
                mma_tf32(acc[jn], a, fbits(wr[0]), fbits(wr[4*W1STR]));
            }
        }
        #pragma unroll
        for (int jn = 0; jn < 4; jn++) {
            int col = nhalf + jn*8 + 2*t;
            float c0 = acc[jn][0] + Bs1[hc*64 + col];
            float c1 = acc[jn][1] + Bs1[hc*64 + col + 1];
            float c2 = acc[jn][2] + Bs1[hc*64 + col];
            float c3 = acc[jn][3] + Bs1[hc*64 + col + 1];
            c0 = (c0 > 0.f) ? c0 : 0.01f*c0;
            c1 = (c1 > 0.f) ? c1 : 0.01f*c1;
            c2 = (c2 > 0.f) ? c2 : 0.01f*c2;
            c3 = (c3 > 0.f) ? c3 : 0.01f*c3;
            float* h0 = &Hcs[(mrow+g)*HCSTR + col];
            float* h1 = &Hcs[(mrow+g+8)*HCSTR + col];
            h0[0] = tf32rna(c0); h0[1] = tf32rna(c1);
            h1[0] = tf32rna(c2); h1[1] = tf32rna(c3);
        }
        __syncthreads();

        // ---- load W2 chunk [64 k][128 n] (reuses Ws) ----
        for (int i = tid; i < 64*32; i += 256) {
            int kk = i >> 5, j4 = i & 31;
            float4 wv = *reinterpret_cast<const float4*>(w2 + (size_t)(hc*64+kk)*CC + j4*4);
            float* d = &Ws[kk*W2STR + j4*4];
            d[0] = tf32rna(wv.x); d[1] = tf32rna(wv.y);
            d[2] = tf32rna(wv.z); d[3] = tf32rna(wv.w);
        }
        __syncthreads();

        // ---- stage 2 partial: acc2 += Hc @ W2c ----
        #pragma unroll
        for (int ks = 0; ks < 8; ks++) {
            uint32_t a[4];
            const float* h0 = &Hcs[(mrow+g)*HCSTR + ks*8];
            const float* h1 = h0 + 8*HCSTR;
            a[0] = fbits(h0[t]); a[1] = fbits(h1[t]);
            a[2] = fbits(h0[t+4]); a[3] = fbits(h1[t+4]);
            #pragma unroll
            for (int n2 = 0; n2 < 2; n2++) {
                #pragma unroll
                for (int jn = 0; jn < 4; jn++) {
                    const float* wr = &Ws[(ks*8+t)*W2STR + n2*64 + nhalf + jn*8 + g];
                    mma_tf32(acc2[n2][jn], a, fbits(wr[0]), fbits(wr[4*W2STR]));
                }
            }
        }
        __syncthreads();
    }

    // ---- write Y into Xs (X dead now) ----
    #pragma unroll
    for (int n2 = 0; n2 < 2; n2++) {
        #pragma unroll
        for (int jn = 0; jn < 4; jn++) {
            int col = n2*64 + nhalf + jn*8 + 2*t;
            float* y0 = &Xs[(mrow+g)*XSTR + col];
            float* y1 = &Xs[(mrow+g+8)*XSTR + col];
            y0[0] = acc2[n2][jn][0] + Bs2[col];
            y0[1] = acc2[n2][jn][1] + Bs2[col+1];
            y1[0] = acc2[n2][jn][2] + Bs2[col];
            y1[1] = acc2[n2][jn][3] + Bs2[col+1];
        }
    }
    __syncthreads();

    if (HAS_RES) {
        const float* rb = res + (size_t)gt0*CC;
        for (int i = tid; i < 64*CC; i += 256) {
            int tt = i >> 7, c = i & 127;
            Xs[tt*XSTR + c] += rb[i];
        }
        __syncthreads();
    }
    if (OUT_CHW) {
        float* ob = out + (size_t)b*CC*SS + s0;
        for (int i = tid; i < 64*CC; i += 256) {
            int c = i >> 6, tt = i & 63;
            ob[c*SS + tt] = Xs[tt*XSTR + c];
        }
    } else {
        float* ob = out + (size_t)gt0*CC;
        for (int i = tid; i < 64*CC; i += 256) {
            int tt = i >> 7, c = i & 127;
            ob[i] = Xs[tt*XSTR + c];
        }
    }
}

// fused q/k/v projections: grid 384, group = blockIdx.x / 128
__global__ __launch_bounds__(256, 2)
void qkv_proj_kernel(QKVArgs a)
{
    const int grp = blockIdx.x >> 7;
    const int bx  = blockIdx.x & 127;
    float* outp = (grp == 0) ? g_qp : (grp == 1) ? g_kp : g_vp;
    const ProjSet& p = a.ps[grp];
    proj_body<0, false, false>(a.in[grp], p.gam, p.bet, p.w1, p.b1, p.w2, p.b2,
                               nullptr, outp, bx);
}

// residual MLPs
template<bool OUT_CHW>
__global__ __launch_bounds__(256, 2)
void mlp_tc_kernel(int in_sel, const float* __restrict__ w1, const float* __restrict__ b1,
                   const float* __restrict__ w2, const float* __restrict__ b2,
                   int res_sel, float* __restrict__ out_ext, int out_sel)
{
    const float* in  = sel_in(in_sel, nullptr);
    const float* res = sel_in(res_sel, nullptr);
    float*       out = sel_out(out_sel, out_ext);
    proj_body<1, true, OUT_CHW>(in, nullptr, nullptr, w1, b1, w2, b2, res, out, blockIdx.x);
}

// ================= mma.sync tf32 flash attention (unchanged, known-good) =================
#define KVSTRIDE 36

__global__ __launch_bounds__(128, 2) void attn_mma_kernel()
{
    __shared__ __align__(16) float Ks[2][64*KVSTRIDE];
    __shared__ __align__(16) float Vs[2][64*KVSTRIDE];

    const int tid  = threadIdx.x;
    const int wid  = tid >> 5;
    const int lane = tid & 31;
    const int g    = lane >> 2;
    const int t    = lane & 3;
    const int h = blockIdx.y, b = blockIdx.z;
    const int q0 = blockIdx.x * 128;

    const float* qg = g_qp + ((size_t)b*SS)*CC + h*DD;
    const float* kg = g_kp + ((size_t)b*SS)*CC + h*DD;
    const float* vg = g_vp + ((size_t)b*SS)*CC + h*DD;

    uint32_t qa[2][4][4];
    #pragma unroll
    for (int mf = 0; mf < 2; mf++) {
        const int r0 = q0 + wid*32 + mf*16 + g;
        const float* qrow0 = qg + (size_t)r0*CC;
        const float* qrow1 = qrow0 + 8*CC;
        #pragma unroll
        for (int kt = 0; kt < 4; kt++) {
            qa[mf][kt][0] = fbits(qrow0[kt*8 + t]     * QS2);
            qa[mf][kt][1] = fbits(qrow1[kt*8 + t]     * QS2);
            qa[mf][kt][2] = fbits(qrow0[kt*8 + t + 4] * QS2);
            qa[mf][kt][3] = fbits(qrow1[kt*8 + t + 4] * QS2);
        }
    }

    float O[2][4][4];
    float m[2][2], l[2][2];
    #pragma unroll
    for (int mf = 0; mf < 2; mf++) {
        #pragma unroll
        for (int j = 0; j < 4; j++)
            #pragma unroll
            for (int i = 0; i < 4; i++) O[mf][j][i] = 0.f;
        m[mf][0] = m[mf][1] = -1e30f;
        l[mf][0] = l[mf][1] = 0.f;
    }

    const int srcA = (lane & ~3) | (t >> 1);
    const int srcB = srcA + 2;

    auto cp_tile = [&](int tile, int buf) {
        #pragma unroll
        for (int r = 0; r < 4; r++) {
            int idx = tid + r*128;
            int row = idx >> 3, c4 = idx & 7;
            size_t goff = (size_t)(tile*64 + row)*CC + c4*4;
            uint32_t kd = (uint32_t)__cvta_generic_to_shared(&Ks[buf][row*KVSTRIDE + c4*4]);
            uint32_t vd = (uint32_t)__cvta_generic_to_shared(&Vs[buf][row*KVSTRIDE + c4*4]);
            asm volatile("cp.async.ca.shared.global [%0], [%1], 16;" :: "r"(kd), "l"(kg + goff));
            asm volatile("cp.async.ca.shared.global [%0], [%1], 16;" :: "r"(vd), "l"(vg + goff));
        }
        asm volatile("cp.async.commit_group;" ::: "memory");
    };

    cp_tile(0, 0);

    for (int tile = 0; tile < SS/64; tile++) {
        const int buf = tile & 1;
        if (tile + 1 < SS/64) {
            cp_tile(tile + 1, buf ^ 1);
            asm volatile("cp.async.wait_group 1;" ::: "memory");
        } else {
            asm volatile("cp.async.wait_group 0;" ::: "memory");
        }
        __syncthreads();

        float s[2][8][4];
        #pragma unroll
        for (int jn = 0; jn < 8; jn++) {
            #pragma unroll
            for (int mf = 0; mf < 2; mf++)
                s[mf][jn][0] = s[mf][jn][1] = s[mf][jn][2] = s[mf][jn][3] = 0.f;
            const float* krow = &Ks[buf][(jn*8 + g)*KVSTRIDE];
            #pragma unroll
            for (int kt = 0; kt < 4; kt++) {
                uint32_t b0 = fbits(krow[kt*8 + t]);
                uint32_t b1 = fbits(krow[kt*8 + t + 4]);
                mma_tf32(s[0][jn], qa[0][kt], b0, b1);
                mma_tf32(s[1][jn], qa[1][kt], b0, b1);
            }
        }

        float corr[2][2];
        #pragma unroll
        for (int mf = 0; mf < 2; mf++) {
            float mt0 = s[mf][0][0], mt1 = s[mf][0][2];
            #pragma unroll
            for (int jn = 0; jn < 8; jn++) {
                mt0 = fmaxf(mt0, fmaxf(s[mf][jn][0], s[mf][jn][1]));
                mt1 = fmaxf(mt1, fmaxf(s[mf][jn][2], s[mf][jn][3]));
            }
            mt0 = fmaxf(mt0, __shfl_xor_sync(0xffffffffu, mt0, 1));
            mt0 = fmaxf(mt0, __shfl_xor_sync(0xffffffffu, mt0, 2));
            mt1 = fmaxf(mt1, __shfl_xor_sync(0xffffffffu, mt1, 1));
            mt1 = fmaxf(mt1, __shfl_xor_sync(0xffffffffu, mt1, 2));
            const float mn0 = fmaxf(m[mf][0], mt0), mn1 = fmaxf(m[mf][1], mt1);
            corr[mf][0] = fexp2(m[mf][0] - mn0);
            corr[mf][1] = fexp2(m[mf][1] - mn1);
            m[mf][0] = mn0; m[mf][1] = mn1;
            float ls0 = 0.f, ls1 = 0.f;
            #pragma unroll
            for (int jn = 0; jn < 8; jn++) {
                s[mf][jn][0] = fexp2(s[mf][jn][0] - mn0); ls0 += s[mf][jn][0];
                s[mf][jn][1] = fexp2(s[mf][jn][1] - mn0); ls0 += s[mf][jn][1];
                s[mf][jn][2] = fexp2(s[mf][jn][2] - mn1); ls1 += s[mf][jn][2];
                s[mf][jn][3] = fexp2(s[mf][jn][3] - mn1); ls1 += s[mf][jn][3];
            }
            l[mf][0] = l[mf][0]*corr[mf][0] + ls0;
            l[mf][1] = l[mf][1]*corr[mf][1] + ls1;
            #pragma unroll
            for (int j = 0; j < 4; j++) {
                O[mf][j][0] *= corr[mf][0]; O[mf][j][1] *= corr[mf][0];
                O[mf][j][2] *= corr[mf][1]; O[mf][j][3] *= corr[mf][1];
            }
        }

        #pragma unroll
        for (int kk = 0; kk < 8; kk++) {
            uint32_t pa[2][4];
            #pragma unroll
            for (int mf = 0; mf < 2; mf++) {
                float v00 = __shfl_sync(0xffffffffu, s[mf][kk][0], srcA);
                float v01 = __shfl_sync(0xffffffffu, s[mf][kk][1], srcA);
                float v20 = __shfl_sync(0xffffffffu, s[mf][kk][2], srcA);
                float v21 = __shfl_sync(0xffffffffu, s[mf][kk][3], srcA);
                float w00 = __shfl_sync(0xffffffffu, s[mf][kk][0], srcB);
                float w01 = __shfl_sync(0xffffffffu, s[mf][kk][1], srcB);
                float w20 = __shfl_sync(0xffffffffu, s[mf][kk][2], srcB);
                float w21 = __shfl_sync(0xffffffffu, s[mf][kk][3], srcB);
                pa[mf][0] = fbits((t & 1) ? v01 : v00);
                pa[mf][1] = fbits((t & 1) ? v21 : v20);
                pa[mf][2] = fbits((t & 1) ? w01 : w00);
                pa[mf][3] = fbits((t & 1) ? w21 : w20);
            }
            const float* vrow0 = &Vs[buf][(kk*8 + t)*KVSTRIDE];
            const float* vrow1 = &Vs[buf][(kk*8 + t + 4)*KVSTRIDE];
            #pragma unroll
            for (int jn = 0; jn < 4; jn++) {
                uint32_t b0 = fbits(vrow0[jn*8 + g]);
                uint32_t b1 = fbits(vrow1[jn*8 + g]);
                mma_tf32(O[0][jn], pa[0], b0, b1);
                mma_tf32(O[1][jn], pa[1], b0, b1);
            }
        }
        __syncthreads();
    }

    #pragma unroll
    for (int mf = 0; mf < 2; mf++) {
        float l0 = l[mf][0], l1 = l[mf][1];
        l0 += __shfl_xor_sync(0xffffffffu, l0, 1);
        l0 += __shfl_xor_sync(0xffffffffu, l0, 2);
        l1 += __shfl_xor_sync(0xffffffffu, l1, 1);
        l1 += __shfl_xor_sync(0xffffffffu, l1, 2);
        const float inv0 = 1.0f / l0, inv1 = 1.0f / l1;
        const int r0 = q0 + wid*32 + mf*16 + g;
        float* o0 = g_x + ((size_t)b*SS + r0)*CC + h*DD;
        float* o1 = o0 + 8*CC;
        #pragma unroll
        for (int jn = 0; jn < 4; jn++) {
            float2 u0 = make_float2(O[mf][jn][0]*inv0, O[mf][jn][1]*inv0);
            float2 u1 = make_float2(O[mf][jn][2]*inv1, O[mf][jn][3]*inv1);
            *reinterpret_cast<float2*>(o0 + jn*8 + 2*t) = u0;
            *reinterpret_cast<float2*>(o1 + jn*8 + 2*t) = u1;
        }
    }
}

// ---------------- launcher ----------------
extern "C" void kernel_launch(void* const* d_in, const int* in_sizes, int n_in,
                              void* d_out, int out_size)
{
    (void)in_sizes; (void)n_in; (void)out_size;
    const float* q      = (const float*)d_in[0];
    const float* k      = (const float*)d_in[1];
    const float* v      = (const float*)d_in[2];
    float* out = (float*)d_out;

    QKVArgs qa;
    qa.in[0] = q; qa.in[1] = k; qa.in[2] = v;
    // q set
    qa.ps[0] = ProjSet{ (const float*)d_in[3], (const float*)d_in[4],
                        (const float*)d_in[5], (const float*)d_in[6],
                        (const float*)d_in[7], (const float*)d_in[8] };
    // k set
    qa.ps[1] = ProjSet{ (const float*)d_in[9], (const float*)d_in[10],
                        (const float*)d_in[11], (const float*)d_in[12],
                        (const float*)d_in[13], (const float*)d_in[14] };
    // v set
    qa.ps[2] = ProjSet{ (const float*)d_in[15], (const float*)d_in[16],
                        (const float*)d_in[17], (const float*)d_in[18],
                        (const float*)d_in[19], (const float*)d_in[20] };

    const float* m1_w1  = (const float*)d_in[21];
    const float* m1_b1  = (const float*)d_in[22];
    const float* m1_w2  = (const float*)d_in[23];
    const float* m1_b2  = (const float*)d_in[24];
    const float* m2_w1  = (const float*)d_in[25];
    const float* m2_b1  = (const float*)d_in[26];
    const float* m2_w2  = (const float*)d_in[27];
    const float* m2_b2  = (const float*)d_in[28];

    cudaFuncSetAttribute(qkv_proj_kernel,
                         cudaFuncAttributeMaxDynamicSharedMemorySize, PROJ_SMEM_BYTES);
    cudaFuncSetAttribute(mlp_tc_kernel<false>,
                         cudaFuncAttributeMaxDynamicSharedMemorySize, PROJ_SMEM_BYTES);
    cudaFuncSetAttribute(mlp_tc_kernel<true>,
                         cudaFuncAttributeMaxDynamicSharedMemorySize, PROJ_SMEM_BYTES);

    // fused q/k/v projections -> g_qp/g_kp/g_vp
    qkv_proj_kernel<<<384, 256, PROJ_SMEM_BYTES>>>(qa);

    // flash attention -> g_x
    attn_mma_kernel<<<dim3(SS/128, NH, BB), 128>>>();

    // rs1 = vp + mlp1(x) -> g_r1
    mlp_tc_kernel<false><<<128, 256, PROJ_SMEM_BYTES>>>(3, m1_w1, m1_b1, m1_w2, m1_b2, 2, nullptr, 4);

    // rs2 = rs1 + mlp2(rs1) -> out (CHW)
    mlp_tc_kernel<true><<<128, 256, PROJ_SMEM_BYTES>>>(4, m2_w1, m2_b1, m2_w2, m2_b2, 4, out, -1);
}